// round 11
// baseline (speedup 1.0000x reference)
#include <cuda_runtime.h>
#include <cuda_fp16.h>
#include <cfloat>
#include <cstdint>

// Problem constants
#define S_LEN   2048
#define BATCH   2
#define HDIM    4096
#define NHEADS  32
#define HEADD   128
#define M_ROWS  4096            // B*S
#define QKV_N   12288           // 3*H
#define INV_NORM 0.08838834764831845f   // 1/sqrt(128)

// Scratch (allocation-free rule: __device__ globals). All half-precision.
__device__ __half g_qkvh[(size_t)M_ROWS * 8192];        // [row][head][{q,k}][128]
__device__ __half g_vth [(size_t)64 * 128 * 2048];      // [b*NH+h][d][s] (V^T)
__device__ __half g_rwh [(size_t)QKV_N * HDIM];         // qkv_w half
__device__ __half g_rhsh[(size_t)M_ROWS * HDIM];        // hs half
__device__ __half g_rw2h[(size_t)HDIM * HDIM];          // dense_w half
__device__ __half g_ctxh[(size_t)M_ROWS * HDIM];        // ctx half
__device__ unsigned char g_mask8[(size_t)BATCH * S_LEN * S_LEN];  // packed mask
__device__ int   g_all_int01;
__device__ int   g_all_f01;

// ---------------------------------------------------------------------------
__global__ void k_set_flags() { g_all_int01 = 1; g_all_f01 = 1; }

__global__ void k_detect(const int* __restrict__ w, int n) {
    for (int i = blockIdx.x * blockDim.x + threadIdx.x; i < n;
         i += gridDim.x * blockDim.x) {
        int v = w[i];
        if ((unsigned)v > 1u) g_all_int01 = 0;
        float f = __int_as_float(v);
        if (!(f == 0.0f || f == 1.0f)) g_all_f01 = 0;
    }
}

// Pack mask (any wire dtype) -> u8 0/1
__global__ void k_pack(const void* __restrict__ in,
                       unsigned char* __restrict__ out, int n4) {
    const int mtype = g_all_int01 ? 1 : (g_all_f01 ? 2 : 0);
    for (int i = blockIdx.x * blockDim.x + threadIdx.x; i < n4;
         i += gridDim.x * blockDim.x) {
        uchar4 o;
        if (mtype == 1) {
            int4 v = ((const int4*)in)[i];
            o = make_uchar4(v.x != 0, v.y != 0, v.z != 0, v.w != 0);
        } else if (mtype == 2) {
            float4 v = ((const float4*)in)[i];
            o = make_uchar4(v.x != 0.f, v.y != 0.f, v.z != 0.f, v.w != 0.f);
        } else {
            uchar4 v = ((const uchar4*)in)[i];
            o = make_uchar4(v.x != 0, v.y != 0, v.z != 0, v.w != 0);
        }
        ((uchar4*)out)[i] = o;
    }
}

// f32 -> packed half2 conversion pass
__global__ void k_cvt(const float4* __restrict__ in, uint2* __restrict__ out,
                      int n4) {
    for (int i = blockIdx.x * blockDim.x + threadIdx.x; i < n4;
         i += gridDim.x * blockDim.x) {
        float4 v = in[i];
        __half2 lo = __float22half2_rn(make_float2(v.x, v.y));
        __half2 hi = __float22half2_rn(make_float2(v.z, v.w));
        uint2 o;
        o.x = *(uint32_t*)&lo;
        o.y = *(uint32_t*)&hi;
        out[i] = o;
    }
}

// ---------------------------------------------------------------------------
// cp.async helpers
// ---------------------------------------------------------------------------
__device__ __forceinline__ void cp16(void* dst, const void* src) {
    uint32_t d = (uint32_t)__cvta_generic_to_shared(dst);
    asm volatile("cp.async.cg.shared.global [%0], [%1], 16;" :: "r"(d), "l"(src));
}
#define CP_COMMIT()  asm volatile("cp.async.commit_group;")
#define CP_WAIT(n)   asm volatile("cp.async.wait_group %0;" :: "n"(n))

// fp16 MMA m16n8k16, f32 accumulate
#define MMA_F16(D, a0, a1, a2, a3, b0, b1)                                    \
    asm volatile(                                                             \
        "mma.sync.aligned.m16n8k16.row.col.f32.f16.f16.f32 "                  \
        "{%0,%1,%2,%3}, {%4,%5,%6,%7}, {%8,%9}, {%0,%1,%2,%3};"               \
        : "+f"(D[0]), "+f"(D[1]), "+f"(D[2]), "+f"(D[3])                      \
        : "r"(a0), "r"(a1), "r"(a2), "r"(a3), "r"(b0), "r"(b1))

// pair barrier: warps 2p and 2p+1 (64 threads), named id p+1 (0 is CTA-wide)
#define BARP(p) asm volatile("bar.sync %0, 64;" :: "r"((p) + 1) : "memory")

// ---------------------------------------------------------------------------
// FP16 GEMM (NT), 3-stage cp.async pipeline.
// Block 128x128, K-tile 64 halves, 256 threads (8 warps 4x2), warp tile 32x64.
// mode 0: f32 out C = acc + bias + resid
// mode 1: qkv split -> g_qkvh (q,k packed half) + g_vth (V^T via smem transpose)
// ---------------------------------------------------------------------------
#define GBK 64                       // K-tile in halves
#define GPAD 36                      // row stride in uint32 (144B)
#define GROWB 144                    // row stride bytes
#define GSTG_B (256 * GROWB)         // 36864 B per stage (A 128 rows + B 128)
#define GNSTG 3
#define GEMM_SMEM_BYTES (GNSTG * GSTG_B)

__global__ __launch_bounds__(256, 2)
void gemm_f16(const __half* __restrict__ A, const __half* __restrict__ W,
              const float* __restrict__ bias, const float* __restrict__ resid,
              float* __restrict__ C, int M, int N, int K, int mode)
{
    extern __shared__ unsigned char gsmb[];

    const int t    = threadIdx.x;
    const int warp = t >> 5;
    const int lane = t & 31;
    const int gid  = lane >> 2;
    const int tig  = lane & 3;
    const int wm   = (warp >> 1) * 32;
    const int wn   = (warp & 1) * 64;

    const int bm = blockIdx.y * 128;
    const int bn = blockIdx.x * 128;
    const int NT = K / GBK;

    float d[2][8][4];
#pragma unroll
    for (int i = 0; i < 2; i++)
#pragma unroll
        for (int j = 0; j < 8; j++)
#pragma unroll
            for (int c = 0; c < 4; c++) d[i][j][c] = 0.f;

    // loader: 256 rows x 8 chunks (16B) = 2048 tasks, 8 per thread
    auto load_stage = [&](int st, int kk0) {
        unsigned char* stg = gsmb + st * GSTG_B;
#pragma unroll
        for (int i = 0; i < 8; i++) {
            const int e = i * 256 + t;
            const int r = e >> 3, c = e & 7;
            const __half* src = (r < 128)
                ? A + (size_t)(bm + r) * K + kk0 + c * 8
                : W + (size_t)(bn + r - 128) * K + kk0 + c * 8;
            cp16(stg + r * GROWB + c * 16, src);
        }
    };

    load_stage(0, 0);    CP_COMMIT();
    load_stage(1, GBK);  CP_COMMIT();

    for (int kt = 0; kt < NT; kt++) {
        const int s = kt % GNSTG;
        CP_WAIT(1);
        __syncthreads();
        if (kt + 2 < NT) load_stage((kt + 2) % GNSTG, (kt + 2) * GBK);
        CP_COMMIT();

        const uint32_t* As = (const uint32_t*)(gsmb + s * GSTG_B);
        const uint32_t* Ws = As + 128 * GPAD;

#pragma unroll
        for (int ks = 0; ks < 4; ks++) {
            uint32_t a[2][4];
#pragma unroll
            for (int mt = 0; mt < 2; mt++) {
                const int r = wm + mt * 16 + gid;
                a[mt][0] = As[r * GPAD + ks * 8 + tig];
                a[mt][1] = As[(r + 8) * GPAD + ks * 8 + tig];
                a[mt][2] = As[r * GPAD + ks * 8 + 4 + tig];
                a[mt][3] = As[(r + 8) * GPAD + ks * 8 + 4 + tig];
            }
            uint32_t b[8][2];
#pragma unroll
            for (int nt = 0; nt < 8; nt++) {
                const int r = wn + nt * 8 + gid;
                b[nt][0] = Ws[r * GPAD + ks * 8 + tig];
                b[nt][1] = Ws[r * GPAD + ks * 8 + 4 + tig];
            }
#pragma unroll
            for (int mt = 0; mt < 2; mt++)
#pragma unroll
                for (int nt = 0; nt < 8; nt++)
                    MMA_F16(d[mt][nt], a[mt][0], a[mt][1], a[mt][2], a[mt][3],
                            b[nt][0], b[nt][1]);
        }
    }

    // ---------------- Epilogue ----------------
    if (mode == 1 && (bn % 384) == 256) {
        // V tile (whole tile is V for head bn/384): transpose via smem,
        // then coalesced 16B half stores along s into g_vth[d][s].
        __syncthreads();                      // pipeline smem now reusable
        float* st = (float*)gsmb;             // 128 cols x 132 floats
#pragma unroll
        for (int mt = 0; mt < 2; mt++) {
            const int rL = wm + mt * 16 + gid;        // local row 0..127
#pragma unroll
            for (int nt = 0; nt < 8; nt++) {
                const int cL = wn + nt * 8 + tig * 2; // local col 0..127
                const float b0 = bias[bn + cL], b1 = bias[bn + cL + 1];
                st[cL * 132 + rL]           = d[mt][nt][0] + b0;
                st[(cL + 1) * 132 + rL]     = d[mt][nt][1] + b1;
                st[cL * 132 + rL + 8]       = d[mt][nt][2] + b0;
                st[(cL + 1) * 132 + rL + 8] = d[mt][nt][3] + b1;
            }
        }
        __syncthreads();
        const int head = bn / 384;
        const int bb = bm >> 11, s0 = bm & 2047;
        __half* vdst = g_vth + (size_t)(bb * 32 + head) * 128 * 2048;
        for (int e = t; e < 2048; e += 256) {
            const int dd = e >> 4;            // 0..127
            const int sL = (e & 15) * 8;      // 0..120
            float4 f0 = *(float4*)&st[dd * 132 + sL];
            float4 f1 = *(float4*)&st[dd * 132 + sL + 4];
            __half2 h0 = __float22half2_rn(make_float2(f0.x, f0.y));
            __half2 h1 = __float22half2_rn(make_float2(f0.z, f0.w));
            __half2 h2 = __float22half2_rn(make_float2(f1.x, f1.y));
            __half2 h3 = __float22half2_rn(make_float2(f1.z, f1.w));
            uint4 pk = make_uint4(*(uint32_t*)&h0, *(uint32_t*)&h1,
                                  *(uint32_t*)&h2, *(uint32_t*)&h3);
            *(uint4*)&vdst[(size_t)dd * 2048 + s0 + sL] = pk;
        }
        return;
    }

#pragma unroll
    for (int mt = 0; mt < 2; mt++) {
        const int r0 = bm + wm + mt * 16 + gid;
#pragma unroll
        for (int nt = 0; nt < 8; nt++) {
            const int col = bn + wn + nt * 8 + tig * 2;
            const float b0 = bias[col], b1 = bias[col + 1];
            float v00 = d[mt][nt][0] + b0, v01 = d[mt][nt][1] + b1;
            float v10 = d[mt][nt][2] + b0, v11 = d[mt][nt][3] + b1;
            if (mode == 0) {
                size_t i0 = (size_t)r0 * N + col;
                size_t i1 = (size_t)(r0 + 8) * N + col;
                const float2 rr0 = *(const float2*)(resid + i0);
                const float2 rr1 = *(const float2*)(resid + i1);
                *(float2*)(C + i0) = make_float2(v00 + rr0.x, v01 + rr0.y);
                *(float2*)(C + i1) = make_float2(v10 + rr1.x, v11 + rr1.y);
            } else {
                // q/k tile (bn%384 is 0 or 128): packed half2 stores
                const int head = col / 384;
                const int rem  = col - head * 384;
                const int part = rem >> 7;           // 0 (q) or 1 (k)
                const int dd   = rem & 127;
                size_t base = (size_t)r0 * 8192 + head * 256 + part * 128 + dd;
                *(__half2*)&g_qkvh[base] =
                    __float22half2_rn(make_float2(v00, v01));
                *(__half2*)&g_qkvh[base + (size_t)8 * 8192] =
                    __float22half2_rn(make_float2(v10, v11));
            }
        }
    }
}

// ---------------------------------------------------------------------------
// FP16 flash attention, double-buffered K/V via cp.async, 2 CTAs/SM.
// Softmax m/l state in registers (per-wc partial l); pair barriers for the
// max exchange and P visibility; u8 packed mask.
// ---------------------------------------------------------------------------
#define BQ 64
#define BKV 64
#define ATTN_NT (S_LEN / BKV)
#define QROWB 272                    // 68 u32
#define VROWB 144                    // 36 u32
#define SROWB 144                    // 36 u32

#define SQ_OFF  0
#define SK_OFF  (SQ_OFF + 64 * QROWB)            // 2 stages of 64*272
#define SVT_OFF (SK_OFF + 2 * 64 * QROWB)        // 2 stages of 128*144
#define SS_OFF  (SVT_OFF + 2 * 128 * VROWB)
#define RED_OFF (SS_OFF + 64 * SROWB)            // 128 floats (4 pairs x 32)
#define ATTN_SMEM_BYTES (RED_OFF + 128 * 4)

__global__ __launch_bounds__(256, 2)
void attn_f16(const float* __restrict__ alibi,
              const unsigned char* __restrict__ mask8,
              __half* __restrict__ ctx)
{
    extern __shared__ unsigned char smem[];
    float* sRed = (float*)(smem + RED_OFF);

    const int t    = threadIdx.x;
    const int warp = t >> 5, lane = t & 31;
    const int gid  = lane >> 2, tig = lane & 3;
    const int wr   = warp >> 1, wc = warp & 1;
    const int hh   = blockIdx.y;
    const int b    = hh / NHEADS;
    const int head = hh % NHEADS;
    const int q0   = blockIdx.x * BQ;
    const int mrow = wr * 16 + gid;
    const int redW = wr * 32 + wc * 16 + gid;         // own slot
    const int redO = wr * 32 + (1 - wc) * 16 + gid;   // partner slot

    const size_t mbase = (size_t)b * S_LEN * S_LEN;

    // Q tile: 64 rows x 16 chunks (256B of halves per row)
    {
        const __half* qsrc = g_qkvh + (size_t)(b * S_LEN + q0) * 8192 + head * 256;
        for (int e = t; e < 1024; e += 256) {
            const int r = e >> 4, c = e & 15;
            cp16(smem + SQ_OFF + r * QROWB + c * 16, qsrc + (size_t)r * 8192 + c * 8);
        }
    }

    const __half* ksrc0 = g_qkvh + (size_t)b * S_LEN * 8192 + head * 256 + 128;
    const __half* vsrc0 = g_vth + (size_t)hh * 128 * 2048;

    auto load_kv = [&](int st, int k0) {
        unsigned char* sK = smem + SK_OFF + st * (64 * QROWB);
        unsigned char* sV = smem + SVT_OFF + st * (128 * VROWB);
        for (int e = t; e < 2048; e += 256) {
            if (e < 1024) {   // K: 64 rows x 16 chunks
                const int r = e >> 4, c = e & 15;
                cp16(sK + r * QROWB + c * 16,
                     ksrc0 + (size_t)(k0 + r) * 8192 + c * 8);
            } else {          // V^T: 128 d-rows x 8 chunks (128B per row)
                const int e2 = e - 1024;
                const int r = e2 >> 3, c = e2 & 7;
                cp16(sV + r * VROWB + c * 16,
                     vsrc0 + (size_t)r * 2048 + k0 + c * 8);
            }
        }
    };

    load_kv(0, 0);
    CP_COMMIT();

    float o[8][4];
#pragma unroll
    for (int nt = 0; nt < 8; nt++)
#pragma unroll
        for (int c = 0; c < 4; c++) o[nt][c] = 0.f;

    // softmax state in registers (rows mrow / mrow+8; l is wc-partial)
    float stMA = -FLT_MAX, stMB = -FLT_MAX;
    float stLA = 0.f, stLB = 0.f;

    for (int kt = 0; kt < ATTN_NT; kt++) {
        const int s  = kt & 1;
        const int k0 = kt * BKV;
        CP_WAIT(0);
        __syncthreads();                          // buffers rotated
        if (kt + 1 < ATTN_NT) load_kv(s ^ 1, k0 + BKV);
        CP_COMMIT();

        const uint32_t* Qp = (const uint32_t*)(smem + SQ_OFF);
        const uint32_t* Kp = (const uint32_t*)(smem + SK_OFF + s * (64 * QROWB));
        const uint32_t* Vp = (const uint32_t*)(smem + SVT_OFF + s * (128 * VROWB));
        uint32_t*       Sp = (uint32_t*)(smem + SS_OFF);

        // Phase 1: S = Q K^T (fp16 k16 steps)
        float d[4][4];
#pragma unroll
        for (int nt = 0; nt < 4; nt++)
#pragma unroll
            for (int c = 0; c < 4; c++) d[nt][c] = 0.f;

#pragma unroll
        for (int ks = 0; ks < 8; ks++) {
            const uint32_t a0 = Qp[mrow * 68 + ks * 8 + tig];
            const uint32_t a1 = Qp[(mrow + 8) * 68 + ks * 8 + tig];
            const uint32_t a2 = Qp[mrow * 68 + ks * 8 + 4 + tig];
            const uint32_t a3 = Qp[(mrow + 8) * 68 + ks * 8 + 4 + tig];
#pragma unroll
            for (int nt = 0; nt < 4; nt++) {
                const int key = wc * 32 + nt * 8 + gid;
                const uint32_t b0 = Kp[key * 68 + ks * 8 + tig];
                const uint32_t b1 = Kp[key * 68 + ks * 8 + 4 + tig];
                MMA_F16(d[nt], a0, a1, a2, a3, b0, b1);
            }
        }

        // alibi + packed-u8 mask in registers
#pragma unroll
        for (int nt = 0; nt < 4; nt++) {
            const int colL = wc * 32 + nt * 8 + tig * 2;
            const int kc   = k0 + colL;
            const float2 al = *(const float2*)(alibi + (size_t)hh * S_LEN + kc);
            const int qrA = q0 + mrow, qrB = qrA + 8;
            const uchar2 m0 = *(const uchar2*)(mask8 + mbase + (size_t)qrA * S_LEN + kc);
            const uchar2 m1 = *(const uchar2*)(mask8 + mbase + (size_t)qrB * S_LEN + kc);
            d[nt][0] = m0.x ? -FLT_MAX : al.x + INV_NORM * d[nt][0];
            d[nt][1] = m0.y ? -FLT_MAX : al.y + INV_NORM * d[nt][1];
            d[nt][2] = m1.x ? -FLT_MAX : al.x + INV_NORM * d[nt][2];
            d[nt][3] = m1.y ? -FLT_MAX : al.y + INV_NORM * d[nt][3];
        }

        // partial row max (this wc's 32 cols) via quad shuffle
        float mAp = -FLT_MAX, mBp = -FLT_MAX;
#pragma unroll
        for (int nt = 0; nt < 4; nt++) {
            mAp = fmaxf(mAp, fmaxf(d[nt][0], d[nt][1]));
            mBp = fmaxf(mBp, fmaxf(d[nt][2], d[nt][3]));
        }
        mAp = fmaxf(mAp, __shfl_xor_sync(0xffffffffu, mAp, 1));
        mAp = fmaxf(mAp, __shfl_xor_sync(0xffffffffu, mAp, 2));
        mBp = fmaxf(mBp, __shfl_xor_sync(0xffffffffu, mBp, 1));
        mBp = fmaxf(mBp, __shfl_xor_sync(0xffffffffu, mBp, 2));
        if (tig == 0) {
            sRed[redW]     = mAp;
            sRed[redW + 8] = mBp;
        }
        BARP(wr);                                 // max exchange within pair

        const float mnA = fmaxf(stMA, fmaxf(mAp, sRed[redO]));
        const float mnB = fmaxf(stMB, fmaxf(mBp, sRed[redO + 8]));
        const float cA = __expf(stMA - mnA);
        const float cB = __expf(stMB - mnB);
        stMA = mnA; stMB = mnB;

        float sumA = 0.f, sumB = 0.f;
#pragma unroll
        for (int nt = 0; nt < 4; nt++) {
            float p00 = __expf(d[nt][0] - mnA);
            float p01 = __expf(d[nt][1] - mnA);
            float p10 = __expf(d[nt][2] - mnB);
            float p11 = __expf(d[nt][3] - mnB);
            sumA += p00 + p01;
            sumB += p10 + p11;
            const int pi = wc * 16 + nt * 4 + tig;   // pair index
            __half2 hA = __float22half2_rn(make_float2(p00, p01));
            __half2 hB = __float22half2_rn(make_float2(p10, p11));
            Sp[mrow * 36 + pi]       = *(uint32_t*)&hA;
            Sp[(mrow + 8) * 36 + pi] = *(uint32_t*)&hB;
        }
        sumA += __shfl_xor_sync(0xffffffffu, sumA, 1);
        sumA += __shfl_xor_sync(0xffffffffu, sumA, 2);
        sumB += __shfl_xor_sync(0xffffffffu, sumB, 1);
        sumB += __shfl_xor_sync(0xffffffffu, sumB, 2);
        stLA = stLA * cA + sumA;                  // wc-partial l
        stLB = stLB * cB + sumB;
        BARP(wr);                                 // P visible within pair

        // Phase 3: O = O*c + P @ V (fp16 k16, V^T natural layout)
#pragma unroll
        for (int nt = 0; nt < 8; nt++) {
            o[nt][0] *= cA; o[nt][1] *= cA;
            o[nt][2] *= cB; o[nt][3] *= cB;
        }
#pragma unroll
        for (int ks = 0; ks < 4; ks++) {
            const uint32_t a0 = Sp[mrow * 36 + ks * 8 + tig];
            const uint32_t a1 = Sp[(mrow + 8) * 36 + ks * 8 + tig];
            const uint32_t a2 = Sp[mrow * 36 + ks * 8 + 4 + tig];
            const uint32_t a3 = Sp[(mrow + 8) * 36 + ks * 8 + 4 + tig];
#pragma unroll
            for (int nt = 0; nt < 8; nt++) {
                const int colD = wc * 64 + nt * 8 + gid;
                const uint32_t b0 = Vp[colD * 36 + ks * 8 + tig];
                const uint32_t b1 = Vp[colD * 36 + ks * 8 + 4 + tig];
                MMA_F16(o[nt], a0, a1, a2, a3, b0, b1);
            }
        }
    }

    // epilogue: merge the two wc-partial l's, divide, store
    if (tig == 0) {
        sRed[redW]     = stLA;
        sRed[redW + 8] = stLB;
    }
    BARP(wr);
    {
        const float lA = 1.0f / (stLA + sRed[redO]);
        const float lB = 1.0f / (stLB + sRed[redO + 8]);
        const int rowA = b * S_LEN + q0 + mrow;
#pragma unroll
        for (int nt = 0; nt < 8; nt++) {
            const int col = head * HEADD + wc * 64 + nt * 8 + tig * 2;
            *(__half2*)&ctx[(size_t)rowA * HDIM + col] =
                __float22half2_rn(make_float2(o[nt][0] * lA, o[nt][1] * lA));
            *(__half2*)&ctx[(size_t)(rowA + 8) * HDIM + col] =
                __float22half2_rn(make_float2(o[nt][2] * lB, o[nt][3] * lB));
        }
    }
}

// ---------------------------------------------------------------------------
extern "C" void kernel_launch(void* const* d_in, const int* in_sizes, int n_in,
                              void* d_out, int out_size)
{
    const float* hs    = (const float*)d_in[0];
    const float* resid = (const float*)d_in[1];
    const float* alibi = (const float*)d_in[2];
    const void*  maskp = d_in[3];
    const float* qkv_w = (const float*)d_in[4];
    const float* qkv_b = (const float*)d_in[5];
    const float* dw    = (const float*)d_in[6];
    const float* db    = (const float*)d_in[7];
    float* out = (float*)d_out;

    __half *rw, *rhs, *rw2, *ctxh;
    unsigned char* mask8;
    cudaGetSymbolAddress((void**)&rw,    g_rwh);
    cudaGetSymbolAddress((void**)&rhs,   g_rhsh);
    cudaGetSymbolAddress((void**)&rw2,   g_rw2h);
    cudaGetSymbolAddress((void**)&ctxh,  g_ctxh);
    cudaGetSymbolAddress((void**)&mask8, g_mask8);

    cudaFuncSetAttribute(gemm_f16, cudaFuncAttributeMaxDynamicSharedMemorySize,
                         GEMM_SMEM_BYTES);
    cudaFuncSetAttribute(attn_f16, cudaFuncAttributeMaxDynamicSharedMemorySize,
                         ATTN_SMEM_BYTES);

    // launches 0-4, so ncu -s 5 profiles gemm1 (launch #5)
    k_set_flags<<<1, 1>>>();
    k_detect<<<256, 256>>>((const int*)maskp, in_sizes[3] / 4);
    k_pack<<<1024, 256>>>(maskp, mask8, in_sizes[3] / 4);
    k_cvt<<<4096, 256>>>((const float4*)qkv_w, (uint2*)rw,
                         (int)((size_t)QKV_N * HDIM / 4));
    k_cvt<<<2048, 256>>>((const float4*)hs, (uint2*)rhs,
                         (int)((size_t)M_ROWS * HDIM / 4));

    // #5: QKV projection (fp16 tensor cores) -> g_qkvh (q,k) + g_vth (V^T)
    gemm_f16<<<dim3(QKV_N / 128, M_ROWS / 128), 256, GEMM_SMEM_BYTES>>>(
        rhs, rw, qkv_b, nullptr, nullptr, M_ROWS, QKV_N, HDIM, 1);

    // dense_w convert (only needed by gemm2)
    k_cvt<<<2048, 256>>>((const float4*)dw, (uint2*)rw2,
                         (int)((size_t)HDIM * HDIM / 4));

    // Flash attention (fp16 tensor cores) -> g_ctxh
    attn_f16<<<dim3(S_LEN / BQ, BATCH * NHEADS), 256, ATTN_SMEM_BYTES>>>(
        alibi, mask8, ctxh);

    // Output projection + bias + residual (fp16 tensor cores, f32 out)
    gemm_f16<<<dim3(HDIM / 128, M_ROWS / 128), 256, GEMM_SMEM_BYTES>>>(
        ctxh, rw2, db, resid, out, M_ROWS, HDIM, HDIM, 0);
}

// round 12
// speedup vs baseline: 1.0286x; 1.0286x over previous
#include <cuda_runtime.h>
#include <cuda_fp16.h>
#include <cfloat>
#include <cstdint>

// Problem constants
#define S_LEN   2048
#define BATCH   2
#define HDIM    4096
#define NHEADS  32
#define HEADD   128
#define M_ROWS  4096            // B*S
#define QKV_N   12288           // 3*H
#define INV_NORM 0.08838834764831845f   // 1/sqrt(128)

// Scratch (allocation-free rule: __device__ globals). All half-precision.
__device__ __half g_qkvh[(size_t)M_ROWS * 8192];        // [row][head][{q,k}][128]
__device__ __half g_vth [(size_t)64 * 128 * 2048];      // [b*NH+h][d][s] (V^T)
__device__ __half g_rwh [(size_t)QKV_N * HDIM];         // qkv_w half
__device__ __half g_rhsh[(size_t)M_ROWS * HDIM];        // hs half
__device__ __half g_rw2h[(size_t)HDIM * HDIM];          // dense_w half
__device__ __half g_ctxh[(size_t)M_ROWS * HDIM];        // ctx half
__device__ unsigned char g_mask8[(size_t)BATCH * S_LEN * S_LEN];  // packed mask
__device__ int   g_all_int01;
__device__ int   g_all_f01;

// ---------------------------------------------------------------------------
__global__ void k_set_flags() { g_all_int01 = 1; g_all_f01 = 1; }

__global__ void k_detect(const int* __restrict__ w, int n) {
    for (int i = blockIdx.x * blockDim.x + threadIdx.x; i < n;
         i += gridDim.x * blockDim.x) {
        int v = w[i];
        if ((unsigned)v > 1u) g_all_int01 = 0;
        float f = __int_as_float(v);
        if (!(f == 0.0f || f == 1.0f)) g_all_f01 = 0;
    }
}

// Pack mask (any wire dtype) -> u8 0/1
__global__ void k_pack(const void* __restrict__ in,
                       unsigned char* __restrict__ out, int n4) {
    const int mtype = g_all_int01 ? 1 : (g_all_f01 ? 2 : 0);
    for (int i = blockIdx.x * blockDim.x + threadIdx.x; i < n4;
         i += gridDim.x * blockDim.x) {
        uchar4 o;
        if (mtype == 1) {
            int4 v = ((const int4*)in)[i];
            o = make_uchar4(v.x != 0, v.y != 0, v.z != 0, v.w != 0);
        } else if (mtype == 2) {
            float4 v = ((const float4*)in)[i];
            o = make_uchar4(v.x != 0.f, v.y != 0.f, v.z != 0.f, v.w != 0.f);
        } else {
            uchar4 v = ((const uchar4*)in)[i];
            o = make_uchar4(v.x != 0, v.y != 0, v.z != 0, v.w != 0);
        }
        ((uchar4*)out)[i] = o;
    }
}

// f32 -> packed half2 conversion pass
__global__ void k_cvt(const float4* __restrict__ in, uint2* __restrict__ out,
                      int n4) {
    for (int i = blockIdx.x * blockDim.x + threadIdx.x; i < n4;
         i += gridDim.x * blockDim.x) {
        float4 v = in[i];
        __half2 lo = __float22half2_rn(make_float2(v.x, v.y));
        __half2 hi = __float22half2_rn(make_float2(v.z, v.w));
        uint2 o;
        o.x = *(uint32_t*)&lo;
        o.y = *(uint32_t*)&hi;
        out[i] = o;
    }
}

// ---------------------------------------------------------------------------
// cp.async helpers
// ---------------------------------------------------------------------------
__device__ __forceinline__ void cp16(void* dst, const void* src) {
    uint32_t d = (uint32_t)__cvta_generic_to_shared(dst);
    asm volatile("cp.async.cg.shared.global [%0], [%1], 16;" :: "r"(d), "l"(src));
}
#define CP_COMMIT()  asm volatile("cp.async.commit_group;")
#define CP_WAIT(n)   asm volatile("cp.async.wait_group %0;" :: "n"(n))

// fp16 MMA m16n8k16, f32 accumulate
#define MMA_F16(D, a0, a1, a2, a3, b0, b1)                                    \
    asm volatile(                                                             \
        "mma.sync.aligned.m16n8k16.row.col.f32.f16.f16.f32 "                  \
        "{%0,%1,%2,%3}, {%4,%5,%6,%7}, {%8,%9}, {%0,%1,%2,%3};"               \
        : "+f"(D[0]), "+f"(D[1]), "+f"(D[2]), "+f"(D[3])                      \
        : "r"(a0), "r"(a1), "r"(a2), "r"(a3), "r"(b0), "r"(b1))

// ---------------------------------------------------------------------------
// FP16 GEMM (NT), 3-stage cp.async pipeline.  (exact R9 version)
// Block 128x128, K-tile 64 halves, 256 threads (8 warps 4x2), warp tile 32x64.
// mode 0: f32 out C = acc + bias + resid
// mode 1: qkv split -> g_qkvh (q,k packed half) + g_vth (V^T scatter stores)
// ---------------------------------------------------------------------------
#define GBK 64                       // K-tile in halves
#define GPAD 36                      // row stride in uint32 (144B)
#define GROWB 144                    // row stride bytes
#define GSTG_B (256 * GROWB)         // 36864 B per stage (A 128 rows + B 128)
#define GNSTG 3
#define GEMM_SMEM_BYTES (GNSTG * GSTG_B)

__global__ __launch_bounds__(256, 2)
void gemm_f16(const __half* __restrict__ A, const __half* __restrict__ W,
              const float* __restrict__ bias, const float* __restrict__ resid,
              float* __restrict__ C, int M, int N, int K, int mode)
{
    extern __shared__ unsigned char gsmb[];

    const int t    = threadIdx.x;
    const int warp = t >> 5;
    const int lane = t & 31;
    const int gid  = lane >> 2;
    const int tig  = lane & 3;
    const int wm   = (warp >> 1) * 32;
    const int wn   = (warp & 1) * 64;

    const int bm = blockIdx.y * 128;
    const int bn = blockIdx.x * 128;
    const int NT = K / GBK;

    float d[2][8][4];
#pragma unroll
    for (int i = 0; i < 2; i++)
#pragma unroll
        for (int j = 0; j < 8; j++)
#pragma unroll
            for (int c = 0; c < 4; c++) d[i][j][c] = 0.f;

    // loader: 256 rows x 8 chunks (16B) = 2048 tasks, 8 per thread
    auto load_stage = [&](int st, int kk0) {
        unsigned char* stg = gsmb + st * GSTG_B;
#pragma unroll
        for (int i = 0; i < 8; i++) {
            const int e = i * 256 + t;
            const int r = e >> 3, c = e & 7;
            const __half* src = (r < 128)
                ? A + (size_t)(bm + r) * K + kk0 + c * 8
                : W + (size_t)(bn + r - 128) * K + kk0 + c * 8;
            cp16(stg + r * GROWB + c * 16, src);
        }
    };

    load_stage(0, 0);    CP_COMMIT();
    load_stage(1, GBK);  CP_COMMIT();

    for (int kt = 0; kt < NT; kt++) {
        const int s = kt % GNSTG;
        CP_WAIT(1);
        __syncthreads();
        if (kt + 2 < NT) load_stage((kt + 2) % GNSTG, (kt + 2) * GBK);
        CP_COMMIT();

        const uint32_t* As = (const uint32_t*)(gsmb + s * GSTG_B);
        const uint32_t* Ws = As + 128 * GPAD;

#pragma unroll
        for (int ks = 0; ks < 4; ks++) {
            uint32_t a[2][4];
#pragma unroll
            for (int mt = 0; mt < 2; mt++) {
                const int r = wm + mt * 16 + gid;
                a[mt][0] = As[r * GPAD + ks * 8 + tig];
                a[mt][1] = As[(r + 8) * GPAD + ks * 8 + tig];
                a[mt][2] = As[r * GPAD + ks * 8 + 4 + tig];
                a[mt][3] = As[(r + 8) * GPAD + ks * 8 + 4 + tig];
            }
            uint32_t b[8][2];
#pragma unroll
            for (int nt = 0; nt < 8; nt++) {
                const int r = wn + nt * 8 + gid;
                b[nt][0] = Ws[r * GPAD + ks * 8 + tig];
                b[nt][1] = Ws[r * GPAD + ks * 8 + 4 + tig];
            }
#pragma unroll
            for (int mt = 0; mt < 2; mt++)
#pragma unroll
                for (int nt = 0; nt < 8; nt++)
                    MMA_F16(d[mt][nt], a[mt][0], a[mt][1], a[mt][2], a[mt][3],
                            b[nt][0], b[nt][1]);
        }
    }

    // Epilogue (R9 scatter version)
#pragma unroll
    for (int mt = 0; mt < 2; mt++) {
        const int r0 = bm + wm + mt * 16 + gid;
#pragma unroll
        for (int nt = 0; nt < 8; nt++) {
            const int col = bn + wn + nt * 8 + tig * 2;
            const float b0 = bias[col], b1 = bias[col + 1];
            float v00 = d[mt][nt][0] + b0, v01 = d[mt][nt][1] + b1;
            float v10 = d[mt][nt][2] + b0, v11 = d[mt][nt][3] + b1;
            if (mode == 0) {
                size_t i0 = (size_t)r0 * N + col;
                size_t i1 = (size_t)(r0 + 8) * N + col;
                const float2 rr0 = *(const float2*)(resid + i0);
                const float2 rr1 = *(const float2*)(resid + i1);
                *(float2*)(C + i0) = make_float2(v00 + rr0.x, v01 + rr0.y);
                *(float2*)(C + i1) = make_float2(v10 + rr1.x, v11 + rr1.y);
            } else {
                const int head = col / 384;
                const int rem  = col - head * 384;
                const int part = rem >> 7;
                const int dd   = rem & 127;
                if (part < 2) {
                    size_t base = (size_t)r0 * 8192 + head * 256 + part * 128 + dd;
                    *(__half2*)&g_qkvh[base] =
                        __float22half2_rn(make_float2(v00, v01));
                    *(__half2*)&g_qkvh[base + (size_t)8 * 8192] =
                        __float22half2_rn(make_float2(v10, v11));
                } else {
                    const int bb = r0 >> 11, s0 = r0 & 2047;
                    size_t vb = ((size_t)(bb * 32 + head) * 128 + dd) * 2048;
                    g_vth[vb + s0]            = __float2half_rn(v00);
                    g_vth[vb + 2048 + s0]     = __float2half_rn(v01);
                    g_vth[vb + s0 + 8]        = __float2half_rn(v10);
                    g_vth[vb + 2048 + s0 + 8] = __float2half_rn(v11);
                }
            }
        }
    }
}

// ---------------------------------------------------------------------------
// FP16 flash attention, BQ=128: each warp owns 16 full rows. P stays in
// registers (C-fragment == A-fragment after half2 pack). Softmax is pure
// quad-shuffle. One __syncthreads per KV tile (buffer rotation).
// ---------------------------------------------------------------------------
#define BQ 128
#define BKV 64
#define ATTN_NT (S_LEN / BKV)

#define SQ_OFF  0
#define SK_OFF  (128 * 272)                       // 34816
#define SVT_OFF (SK_OFF + 2 * 64 * 272)           // 69632
#define ATTN_SMEM_BYTES (SVT_OFF + 2 * 128 * 144) // 106496

__global__ __launch_bounds__(256, 1)
void attn_f16(const float* __restrict__ alibi,
              const unsigned char* __restrict__ mask8,
              __half* __restrict__ ctx)
{
    extern __shared__ unsigned char smem[];

    const int t    = threadIdx.x;
    const int warp = t >> 5, lane = t & 31;
    const int gid  = lane >> 2, tig = lane & 3;
    const int hh   = blockIdx.y;
    const int b    = hh / NHEADS;
    const int head = hh % NHEADS;
    const int q0   = blockIdx.x * BQ;
    const int mrow = warp * 16 + gid;             // local row (and +8)

    const size_t mbase = (size_t)b * S_LEN * S_LEN;

    // Q tile: 128 rows x 16 chunks (256B of halves per row)
    {
        const __half* qsrc = g_qkvh + (size_t)(b * S_LEN + q0) * 8192 + head * 256;
        for (int e = t; e < 2048; e += 256) {
            const int r = e >> 4, c = e & 15;
            cp16(smem + SQ_OFF + r * 272 + c * 16, qsrc + (size_t)r * 8192 + c * 8);
        }
    }

    const __half* ksrc0 = g_qkvh + (size_t)b * S_LEN * 8192 + head * 256 + 128;
    const __half* vsrc0 = g_vth + (size_t)hh * 128 * 2048;

    auto load_kv = [&](int st, int k0) {
        unsigned char* sK = smem + SK_OFF + st * (64 * 272);
        unsigned char* sV = smem + SVT_OFF + st * (128 * 144);
        for (int e = t; e < 2048; e += 256) {
            if (e < 1024) {   // K: 64 rows x 16 chunks
                const int r = e >> 4, c = e & 15;
                cp16(sK + r * 272 + c * 16,
                     ksrc0 + (size_t)(k0 + r) * 8192 + c * 8);
            } else {          // V^T: 128 d-rows x 8 chunks (128B per row)
                const int e2 = e - 1024;
                const int r = e2 >> 3, c = e2 & 7;
                cp16(sV + r * 144 + c * 16,
                     vsrc0 + (size_t)r * 2048 + k0 + c * 8);
            }
        }
    };

    load_kv(0, 0);
    CP_COMMIT();

    float o[16][4];
#pragma unroll
    for (int nt = 0; nt < 16; nt++)
#pragma unroll
        for (int c = 0; c < 4; c++) o[nt][c] = 0.f;

    // softmax state in registers; rows fully warp-owned
    float stMA = -FLT_MAX, stMB = -FLT_MAX;
    float stLA = 0.f, stLB = 0.f;

    for (int kt = 0; kt < ATTN_NT; kt++) {
        const int s  = kt & 1;
        const int k0 = kt * BKV;
        CP_WAIT(0);
        __syncthreads();                          // buffers rotated
        if (kt + 1 < ATTN_NT) load_kv(s ^ 1, k0 + BKV);
        CP_COMMIT();

        const uint32_t* Qp = (const uint32_t*)(smem + SQ_OFF);
        const uint32_t* Kp = (const uint32_t*)(smem + SK_OFF + s * (64 * 272));
        const uint32_t* Vp = (const uint32_t*)(smem + SVT_OFF + s * (128 * 144));

        // Phase 1: S = Q K^T, warp tile 16x64 (8 nt x 8 ks MMAs)
        float d[8][4];
#pragma unroll
        for (int nt = 0; nt < 8; nt++)
#pragma unroll
            for (int c = 0; c < 4; c++) d[nt][c] = 0.f;

#pragma unroll
        for (int ks = 0; ks < 8; ks++) {
            const uint32_t a0 = Qp[mrow * 68 + ks * 8 + tig];
            const uint32_t a1 = Qp[(mrow + 8) * 68 + ks * 8 + tig];
            const uint32_t a2 = Qp[mrow * 68 + ks * 8 + 4 + tig];
            const uint32_t a3 = Qp[(mrow + 8) * 68 + ks * 8 + 4 + tig];
#pragma unroll
            for (int nt = 0; nt < 8; nt++) {
                const int key = nt * 8 + gid;
                const uint32_t b0 = Kp[key * 68 + ks * 8 + tig];
                const uint32_t b1 = Kp[key * 68 + ks * 8 + 4 + tig];
                MMA_F16(d[nt], a0, a1, a2, a3, b0, b1);
            }
        }

        // alibi + packed-u8 mask in registers (cols nt*8+2tig over 0..63)
#pragma unroll
        for (int nt = 0; nt < 8; nt++) {
            const int colL = nt * 8 + tig * 2;
            const int kc   = k0 + colL;
            const float2 al = *(const float2*)(alibi + (size_t)hh * S_LEN + kc);
            const int qrA = q0 + mrow, qrB = qrA + 8;
            const uchar2 m0 = *(const uchar2*)(mask8 + mbase + (size_t)qrA * S_LEN + kc);
            const uchar2 m1 = *(const uchar2*)(mask8 + mbase + (size_t)qrB * S_LEN + kc);
            d[nt][0] = m0.x ? -FLT_MAX : al.x + INV_NORM * d[nt][0];
            d[nt][1] = m0.y ? -FLT_MAX : al.y + INV_NORM * d[nt][1];
            d[nt][2] = m1.x ? -FLT_MAX : al.x + INV_NORM * d[nt][2];
            d[nt][3] = m1.y ? -FLT_MAX : al.y + INV_NORM * d[nt][3];
        }

        // full row max via quad shuffle (row owned by this warp's quad)
        float mAp = -FLT_MAX, mBp = -FLT_MAX;
#pragma unroll
        for (int nt = 0; nt < 8; nt++) {
            mAp = fmaxf(mAp, fmaxf(d[nt][0], d[nt][1]));
            mBp = fmaxf(mBp, fmaxf(d[nt][2], d[nt][3]));
        }
        mAp = fmaxf(mAp, __shfl_xor_sync(0xffffffffu, mAp, 1));
        mAp = fmaxf(mAp, __shfl_xor_sync(0xffffffffu, mAp, 2));
        mBp = fmaxf(mBp, __shfl_xor_sync(0xffffffffu, mBp, 1));
        mBp = fmaxf(mBp, __shfl_xor_sync(0xffffffffu, mBp, 2));

        const float mnA = fmaxf(stMA, mAp);
        const float mnB = fmaxf(stMB, mBp);
        const float cA = __expf(stMA - mnA);
        const float cB = __expf(stMB - mnB);
        stMA = mnA; stMB = mnB;

        // exp + pack P into A-fragments (registers only)
        uint32_t paA[8], paB[8];
        float sumA = 0.f, sumB = 0.f;
#pragma unroll
        for (int nt = 0; nt < 8; nt++) {
            float p00 = __expf(d[nt][0] - mnA);
            float p01 = __expf(d[nt][1] - mnA);
            float p10 = __expf(d[nt][2] - mnB);
            float p11 = __expf(d[nt][3] - mnB);
            sumA += p00 + p01;
            sumB += p10 + p11;
            __half2 hA = __float22half2_rn(make_float2(p00, p01));
            __half2 hB = __float22half2_rn(make_float2(p10, p11));
            paA[nt] = *(uint32_t*)&hA;
            paB[nt] = *(uint32_t*)&hB;
        }
        sumA += __shfl_xor_sync(0xffffffffu, sumA, 1);
        sumA += __shfl_xor_sync(0xffffffffu, sumA, 2);
        sumB += __shfl_xor_sync(0xffffffffu, sumB, 1);
        sumB += __shfl_xor_sync(0xffffffffu, sumB, 2);
        stLA = stLA * cA + sumA;
        stLB = stLB * cB + sumB;

        // Phase 3: O = O*c + P @ V (warp tile 16x128, A from registers)
#pragma unroll
        for (int nt = 0; nt < 16; nt++) {
            o[nt][0] *= cA; o[nt][1] *= cA;
            o[nt][2] *= cB; o[nt][3] *= cB;
        }
#pragma unroll
        for (int ks = 0; ks < 4; ks++) {
            const uint32_t a0 = paA[2 * ks];
            const uint32_t a1 = paB[2 * ks];
            const uint32_t a2 = paA[2 * ks + 1];
            const uint32_t a3 = paB[2 * ks + 1];
#pragma unroll
            for (int nt = 0; nt < 16; nt++) {
                const int colD = nt * 8 + gid;
                const uint32_t b0 = Vp[colD * 36 + ks * 8 + tig];
                const uint32_t b1 = Vp[colD * 36 + ks * 8 + 4 + tig];
                MMA_F16(o[nt], a0, a1, a2, a3, b0, b1);
            }
        }
    }

    // epilogue: warp-local l, divide, store
    {
        const float lA = 1.0f / stLA;
        const float lB = 1.0f / stLB;
        const int rowA = b * S_LEN + q0 + mrow;
#pragma unroll
        for (int nt = 0; nt < 16; nt++) {
            const int col = head * HEADD + nt * 8 + tig * 2;
            *(__half2*)&ctx[(size_t)rowA * HDIM + col] =
                __float22half2_rn(make_float2(o[nt][0] * lA, o[nt][1] * lA));
            *(__half2*)&ctx[(size_t)(rowA + 8) * HDIM + col] =
                __float22half2_rn(make_float2(o[nt][2] * lB, o[nt][3] * lB));
        }
    }
}

// ---------------------------------------------------------------------------
extern "C" void kernel_launch(void* const* d_in, const int* in_sizes, int n_in,
                              void* d_out, int out_size)
{
    const float* hs    = (const float*)d_in[0];
    const float* resid = (const float*)d_in[1];
    const float* alibi = (const float*)d_in[2];
    const void*  maskp = d_in[3];
    const float* qkv_w = (const float*)d_in[4];
    const float* qkv_b = (const float*)d_in[5];
    const float* dw    = (const float*)d_in[6];
    const float* db    = (const float*)d_in[7];
    float* out = (float*)d_out;

    __half *rw, *rhs, *rw2, *ctxh;
    unsigned char* mask8;
    cudaGetSymbolAddress((void**)&rw,    g_rwh);
    cudaGetSymbolAddress((void**)&rhs,   g_rhsh);
    cudaGetSymbolAddress((void**)&rw2,   g_rw2h);
    cudaGetSymbolAddress((void**)&ctxh,  g_ctxh);
    cudaGetSymbolAddress((void**)&mask8, g_mask8);

    cudaFuncSetAttribute(gemm_f16, cudaFuncAttributeMaxDynamicSharedMemorySize,
                         GEMM_SMEM_BYTES);
    cudaFuncSetAttribute(attn_f16, cudaFuncAttributeMaxDynamicSharedMemorySize,
                         ATTN_SMEM_BYTES);

    k_set_flags<<<1, 1>>>();
    k_detect<<<256, 256>>>((const int*)maskp, in_sizes[3] / 4);
    k_pack<<<1024, 256>>>(maskp, mask8, in_sizes[3] / 4);
    k_cvt<<<4096, 256>>>((const float4*)qkv_w, (uint2*)rw,
                         (int)((size_t)QKV_N * HDIM / 4));
    k_cvt<<<2048, 256>>>((const float4*)hs, (uint2*)rhs,
                         (int)((size_t)M_ROWS * HDIM / 4));

    // QKV projection (fp16 tensor cores) -> g_qkvh (q,k) + g_vth (V^T)
    gemm_f16<<<dim3(QKV_N / 128, M_ROWS / 128), 256, GEMM_SMEM_BYTES>>>(
        rhs, rw, qkv_b, nullptr, nullptr, M_ROWS, QKV_N, HDIM, 1);

    // dense_w convert (only needed by gemm2)
    k_cvt<<<2048, 256>>>((const float4*)dw, (uint2*)rw2,
                         (int)((size_t)HDIM * HDIM / 4));

    // Flash attention (BQ=128, register-resident P) -> g_ctxh
    attn_f16<<<dim3(S_LEN / BQ, BATCH * NHEADS), 256, ATTN_SMEM_BYTES>>>(
        alibi, mask8, ctxh);

    // Output projection + bias + residual (fp16 tensor cores, f32 out)
    gemm_f16<<<dim3(HDIM / 128, M_ROWS / 128), 256, GEMM_SMEM_BYTES>>>(
        ctxh, rw2, db, resid, out, M_ROWS, HDIM, HDIM, 0);
}

// round 13
// speedup vs baseline: 1.0839x; 1.0537x over previous
#include <cuda_runtime.h>
#include <cuda_fp16.h>
#include <cfloat>
#include <cstdint>

// Problem constants
#define S_LEN   2048
#define BATCH   2
#define HDIM    4096
#define NHEADS  32
#define HEADD   128
#define M_ROWS  4096            // B*S
#define QKV_N   12288           // 3*H
#define INV_NORM 0.08838834764831845f   // 1/sqrt(128)
#define MASK_WORDS (BATCH * S_LEN * S_LEN / 32)   // 262144 u32 = 1MB

// Scratch (allocation-free rule: __device__ globals). All half-precision.
__device__ __half g_qkvh[(size_t)M_ROWS * 8192];        // [row][head][{q,k}][128]
__device__ __half g_vth [(size_t)64 * 128 * 2048];      // [b*NH+h][d][s] (V^T)
__device__ __half g_rwh [(size_t)QKV_N * HDIM];         // qkv_w half
__device__ __half g_rhsh[(size_t)M_ROWS * HDIM];        // hs half
__device__ __half g_rw2h[(size_t)HDIM * HDIM];          // dense_w half
__device__ __half g_ctxh[(size_t)M_ROWS * HDIM];        // ctx half
__device__ uint32_t g_maskw[MASK_WORDS];                // bit-packed mask
__device__ int   g_all_int01;
__device__ int   g_all_f01;

// ---------------------------------------------------------------------------
__global__ void k_set_flags() { g_all_int01 = 1; g_all_f01 = 1; }

__global__ void k_detect(const int* __restrict__ w, int n) {
    for (int i = blockIdx.x * blockDim.x + threadIdx.x; i < n;
         i += gridDim.x * blockDim.x) {
        int v = w[i];
        if ((unsigned)v > 1u) g_all_int01 = 0;
        float f = __int_as_float(v);
        if (!(f == 0.0f || f == 1.0f)) g_all_f01 = 0;
    }
}

// Pack mask (any wire dtype) -> 1 bit per element
__global__ void k_pack_bits(const void* __restrict__ in,
                            uint32_t* __restrict__ out, int nwords) {
    const int mtype = g_all_int01 ? 1 : (g_all_f01 ? 2 : 0);
    for (int w = blockIdx.x * blockDim.x + threadIdx.x; w < nwords;
         w += gridDim.x * blockDim.x) {
        uint32_t bits = 0;
        if (mtype == 1) {
            const int4* p = (const int4*)in + (size_t)w * 8;
#pragma unroll
            for (int j = 0; j < 8; j++) {
                int4 v = p[j];
                bits |= (v.x != 0 ? 1u : 0u) << (j * 4 + 0);
                bits |= (v.y != 0 ? 1u : 0u) << (j * 4 + 1);
                bits |= (v.z != 0 ? 1u : 0u) << (j * 4 + 2);
                bits |= (v.w != 0 ? 1u : 0u) << (j * 4 + 3);
            }
        } else if (mtype == 2) {
            const float4* p = (const float4*)in + (size_t)w * 8;
#pragma unroll
            for (int j = 0; j < 8; j++) {
                float4 v = p[j];
                bits |= (v.x != 0.f ? 1u : 0u) << (j * 4 + 0);
                bits |= (v.y != 0.f ? 1u : 0u) << (j * 4 + 1);
                bits |= (v.z != 0.f ? 1u : 0u) << (j * 4 + 2);
                bits |= (v.w != 0.f ? 1u : 0u) << (j * 4 + 3);
            }
        } else {
            const uint4* p = (const uint4*)in + (size_t)w * 2;
#pragma unroll
            for (int j = 0; j < 2; j++) {
                uint4 v = p[j];
                const uint32_t ws[4] = {v.x, v.y, v.z, v.w};
#pragma unroll
                for (int q = 0; q < 4; q++)
#pragma unroll
                    for (int bb = 0; bb < 4; bb++)
                        bits |= (((ws[q] >> (bb * 8)) & 0xFFu) != 0 ? 1u : 0u)
                                << (j * 16 + q * 4 + bb);
            }
        }
        out[w] = bits;
    }
}

// Fused f32 -> packed half2 conversion for all three operand arrays
__global__ void k_cvt3(const float4* __restrict__ i1, uint2* __restrict__ o1, int n1,
                       const float4* __restrict__ i2, uint2* __restrict__ o2, int n2,
                       const float4* __restrict__ i3, uint2* __restrict__ o3, int n3)
{
    const int total = n1 + n2 + n3;
    for (int i = blockIdx.x * blockDim.x + threadIdx.x; i < total;
         i += gridDim.x * blockDim.x) {
        const float4* src; uint2* dst; int j;
        if (i < n1)           { src = i1; dst = o1; j = i; }
        else if (i < n1 + n2) { src = i2; dst = o2; j = i - n1; }
        else                  { src = i3; dst = o3; j = i - n1 - n2; }
        float4 v = src[j];
        __half2 lo = __float22half2_rn(make_float2(v.x, v.y));
        __half2 hi = __float22half2_rn(make_float2(v.z, v.w));
        uint2 o;
        o.x = *(uint32_t*)&lo;
        o.y = *(uint32_t*)&hi;
        dst[j] = o;
    }
}

// ---------------------------------------------------------------------------
// cp.async helpers
// ---------------------------------------------------------------------------
__device__ __forceinline__ void cp16(void* dst, const void* src) {
    uint32_t d = (uint32_t)__cvta_generic_to_shared(dst);
    asm volatile("cp.async.cg.shared.global [%0], [%1], 16;" :: "r"(d), "l"(src));
}
#define CP_COMMIT()  asm volatile("cp.async.commit_group;")
#define CP_WAIT(n)   asm volatile("cp.async.wait_group %0;" :: "n"(n))

// fp16 MMA m16n8k16, f32 accumulate
#define MMA_F16(D, a0, a1, a2, a3, b0, b1)                                    \
    asm volatile(                                                             \
        "mma.sync.aligned.m16n8k16.row.col.f32.f16.f16.f32 "                  \
        "{%0,%1,%2,%3}, {%4,%5,%6,%7}, {%8,%9}, {%0,%1,%2,%3};"               \
        : "+f"(D[0]), "+f"(D[1]), "+f"(D[2]), "+f"(D[3])                      \
        : "r"(a0), "r"(a1), "r"(a2), "r"(a3), "r"(b0), "r"(b1))

// ---------------------------------------------------------------------------
// FP16 GEMM (NT), 3-stage cp.async pipeline.  (R9/R12 proven version)
// Block 128x128, K-tile 64 halves, 256 threads (8 warps 4x2), warp tile 32x64.
// mode 0: f32 out C = acc + bias + resid
// mode 1: qkv split -> g_qkvh (q,k packed half) + g_vth (V^T scatter stores)
// ---------------------------------------------------------------------------
#define GBK 64                       // K-tile in halves
#define GPAD 36                      // row stride in uint32 (144B)
#define GROWB 144                    // row stride bytes
#define GSTG_B (256 * GROWB)         // 36864 B per stage (A 128 rows + B 128)
#define GNSTG 3
#define GEMM_SMEM_BYTES (GNSTG * GSTG_B)

__global__ __launch_bounds__(256, 2)
void gemm_f16(const __half* __restrict__ A, const __half* __restrict__ W,
              const float* __restrict__ bias, const float* __restrict__ resid,
              float* __restrict__ C, int M, int N, int K, int mode)
{
    extern __shared__ unsigned char gsmb[];

    const int t    = threadIdx.x;
    const int warp = t >> 5;
    const int lane = t & 31;
    const int gid  = lane >> 2;
    const int tig  = lane & 3;
    const int wm   = (warp >> 1) * 32;
    const int wn   = (warp & 1) * 64;

    const int bm = blockIdx.y * 128;
    const int bn = blockIdx.x * 128;
    const int NT = K / GBK;

    float d[2][8][4];
#pragma unroll
    for (int i = 0; i < 2; i++)
#pragma unroll
        for (int j = 0; j < 8; j++)
#pragma unroll
            for (int c = 0; c < 4; c++) d[i][j][c] = 0.f;

    // loader: 256 rows x 8 chunks (16B) = 2048 tasks, 8 per thread
    auto load_stage = [&](int st, int kk0) {
        unsigned char* stg = gsmb + st * GSTG_B;
#pragma unroll
        for (int i = 0; i < 8; i++) {
            const int e = i * 256 + t;
            const int r = e >> 3, c = e & 7;
            const __half* src = (r < 128)
                ? A + (size_t)(bm + r) * K + kk0 + c * 8
                : W + (size_t)(bn + r - 128) * K + kk0 + c * 8;
            cp16(stg + r * GROWB + c * 16, src);
        }
    };

    load_stage(0, 0);    CP_COMMIT();
    load_stage(1, GBK);  CP_COMMIT();

    for (int kt = 0; kt < NT; kt++) {
        const int s = kt % GNSTG;
        CP_WAIT(1);
        __syncthreads();
        if (kt + 2 < NT) load_stage((kt + 2) % GNSTG, (kt + 2) * GBK);
        CP_COMMIT();

        const uint32_t* As = (const uint32_t*)(gsmb + s * GSTG_B);
        const uint32_t* Ws = As + 128 * GPAD;

#pragma unroll
        for (int ks = 0; ks < 4; ks++) {
            uint32_t a[2][4];
#pragma unroll
            for (int mt = 0; mt < 2; mt++) {
                const int r = wm + mt * 16 + gid;
                a[mt][0] = As[r * GPAD + ks * 8 + tig];
                a[mt][1] = As[(r + 8) * GPAD + ks * 8 + tig];
                a[mt][2] = As[r * GPAD + ks * 8 + 4 + tig];
                a[mt][3] = As[(r + 8) * GPAD + ks * 8 + 4 + tig];
            }
            uint32_t b[8][2];
#pragma unroll
            for (int nt = 0; nt < 8; nt++) {
                const int r = wn + nt * 8 + gid;
                b[nt][0] = Ws[r * GPAD + ks * 8 + tig];
                b[nt][1] = Ws[r * GPAD + ks * 8 + 4 + tig];
            }
#pragma unroll
            for (int mt = 0; mt < 2; mt++)
#pragma unroll
                for (int nt = 0; nt < 8; nt++)
                    MMA_F16(d[mt][nt], a[mt][0], a[mt][1], a[mt][2], a[mt][3],
                            b[nt][0], b[nt][1]);
        }
    }

    // Epilogue (scatter version — R9/R12 proven)
#pragma unroll
    for (int mt = 0; mt < 2; mt++) {
        const int r0 = bm + wm + mt * 16 + gid;
#pragma unroll
        for (int nt = 0; nt < 8; nt++) {
            const int col = bn + wn + nt * 8 + tig * 2;
            const float b0 = bias[col], b1 = bias[col + 1];
            float v00 = d[mt][nt][0] + b0, v01 = d[mt][nt][1] + b1;
            float v10 = d[mt][nt][2] + b0, v11 = d[mt][nt][3] + b1;
            if (mode == 0) {
                size_t i0 = (size_t)r0 * N + col;
                size_t i1 = (size_t)(r0 + 8) * N + col;
                const float2 rr0 = *(const float2*)(resid + i0);
                const float2 rr1 = *(const float2*)(resid + i1);
                *(float2*)(C + i0) = make_float2(v00 + rr0.x, v01 + rr0.y);
                *(float2*)(C + i1) = make_float2(v10 + rr1.x, v11 + rr1.y);
            } else {
                const int head = col / 384;
                const int rem  = col - head * 384;
                const int part = rem >> 7;
                const int dd   = rem & 127;
                if (part < 2) {
                    size_t base = (size_t)r0 * 8192 + head * 256 + part * 128 + dd;
                    *(__half2*)&g_qkvh[base] =
                        __float22half2_rn(make_float2(v00, v01));
                    *(__half2*)&g_qkvh[base + (size_t)8 * 8192] =
                        __float22half2_rn(make_float2(v10, v11));
                } else {
                    const int bb = r0 >> 11, s0 = r0 & 2047;
                    size_t vb = ((size_t)(bb * 32 + head) * 128 + dd) * 2048;
                    g_vth[vb + s0]            = __float2half_rn(v00);
                    g_vth[vb + 2048 + s0]     = __float2half_rn(v01);
                    g_vth[vb + s0 + 8]        = __float2half_rn(v10);
                    g_vth[vb + 2048 + s0 + 8] = __float2half_rn(v11);
                }
            }
        }
    }
}

// ---------------------------------------------------------------------------
// FP16 flash attention, BQ=128: each warp owns 16 full rows. P stays in
// registers (C-fragment == A-fragment after half2 pack). Softmax is pure
// quad-shuffle. One __syncthreads per KV tile. Bit-packed mask (L2-resident).
// ---------------------------------------------------------------------------
#define BQ 128
#define BKV 64
#define ATTN_NT (S_LEN / BKV)

#define SQ_OFF  0
#define SK_OFF  (128 * 272)                       // 34816
#define SVT_OFF (SK_OFF + 2 * 64 * 272)           // 69632
#define ATTN_SMEM_BYTES (SVT_OFF + 2 * 128 * 144) // 106496

__global__ __launch_bounds__(256, 1)
void attn_f16(const float* __restrict__ alibi,
              const uint32_t* __restrict__ maskw,
              __half* __restrict__ ctx)
{
    extern __shared__ unsigned char smem[];

    const int t    = threadIdx.x;
    const int warp = t >> 5, lane = t & 31;
    const int gid  = lane >> 2, tig = lane & 3;
    const int hh   = blockIdx.y;
    const int b    = hh / NHEADS;
    const int head = hh % NHEADS;
    const int q0   = blockIdx.x * BQ;
    const int mrow = warp * 16 + gid;             // local row (and +8)

    const uint32_t* mw = maskw + (size_t)b * (S_LEN * S_LEN / 32);

    // Q tile: 128 rows x 16 chunks (256B of halves per row)
    {
        const __half* qsrc = g_qkvh + (size_t)(b * S_LEN + q0) * 8192 + head * 256;
        for (int e = t; e < 2048; e += 256) {
            const int r = e >> 4, c = e & 15;
            cp16(smem + SQ_OFF + r * 272 + c * 16, qsrc + (size_t)r * 8192 + c * 8);
        }
    }

    const __half* ksrc0 = g_qkvh + (size_t)b * S_LEN * 8192 + head * 256 + 128;
    const __half* vsrc0 = g_vth + (size_t)hh * 128 * 2048;

    auto load_kv = [&](int st, int k0) {
        unsigned char* sK = smem + SK_OFF + st * (64 * 272);
        unsigned char* sV = smem + SVT_OFF + st * (128 * 144);
        for (int e = t; e < 2048; e += 256) {
            if (e < 1024) {   // K: 64 rows x 16 chunks
                const int r = e >> 4, c = e & 15;
                cp16(sK + r * 272 + c * 16,
                     ksrc0 + (size_t)(k0 + r) * 8192 + c * 8);
            } else {          // V^T: 128 d-rows x 8 chunks (128B per row)
                const int e2 = e - 1024;
                const int r = e2 >> 3, c = e2 & 7;
                cp16(sV + r * 144 + c * 16,
                     vsrc0 + (size_t)r * 2048 + k0 + c * 8);
            }
        }
    };

    load_kv(0, 0);
    CP_COMMIT();

    float o[16][4];
#pragma unroll
    for (int nt = 0; nt < 16; nt++)
#pragma unroll
        for (int c = 0; c < 4; c++) o[nt][c] = 0.f;

    // softmax state in registers; rows fully warp-owned
    float stMA = -FLT_MAX, stMB = -FLT_MAX;
    float stLA = 0.f, stLB = 0.f;

    for (int kt = 0; kt < ATTN_NT; kt++) {
        const int s  = kt & 1;
        const int k0 = kt * BKV;
        CP_WAIT(0);
        __syncthreads();                          // buffers rotated
        if (kt + 1 < ATTN_NT) load_kv(s ^ 1, k0 + BKV);
        CP_COMMIT();

        const uint32_t* Qp = (const uint32_t*)(smem + SQ_OFF);
        const uint32_t* Kp = (const uint32_t*)(smem + SK_OFF + s * (64 * 272));
        const uint32_t* Vp = (const uint32_t*)(smem + SVT_OFF + s * (128 * 144));

        // Phase 1: S = Q K^T, warp tile 16x64 (8 nt x 8 ks MMAs)
        float d[8][4];
#pragma unroll
        for (int nt = 0; nt < 8; nt++)
#pragma unroll
            for (int c = 0; c < 4; c++) d[nt][c] = 0.f;

#pragma unroll
        for (int ks = 0; ks < 8; ks++) {
            const uint32_t a0 = Qp[mrow * 68 + ks * 8 + tig];
            const uint32_t a1 = Qp[(mrow + 8) * 68 + ks * 8 + tig];
            const uint32_t a2 = Qp[mrow * 68 + ks * 8 + 4 + tig];
            const uint32_t a3 = Qp[(mrow + 8) * 68 + ks * 8 + 4 + tig];
#pragma unroll
            for (int nt = 0; nt < 8; nt++) {
                const int key = nt * 8 + gid;
                const uint32_t b0 = Kp[key * 68 + ks * 8 + tig];
                const uint32_t b1 = Kp[key * 68 + ks * 8 + 4 + tig];
                MMA_F16(d[nt], a0, a1, a2, a3, b0, b1);
            }
        }

        // alibi + bit-packed mask in registers (cols nt*8+2tig over 0..63)
        const int qrA = q0 + mrow, qrB = qrA + 8;
        const uint2 wA = *(const uint2*)&mw[qrA * 64 + (k0 >> 5)];
        const uint2 wB = *(const uint2*)&mw[qrB * 64 + (k0 >> 5)];
#pragma unroll
        for (int nt = 0; nt < 8; nt++) {
            const int colL = nt * 8 + tig * 2;
            const int kc   = k0 + colL;
            const float2 al = *(const float2*)(alibi + (size_t)hh * S_LEN + kc);
            const int sh = (nt & 3) * 8 + tig * 2;
            const uint32_t bA = ((nt < 4) ? wA.x : wA.y) >> sh;
            const uint32_t bB = ((nt < 4) ? wB.x : wB.y) >> sh;
            d[nt][0] = (bA & 1) ? -FLT_MAX : al.x + INV_NORM * d[nt][0];
            d[nt][1] = (bA & 2) ? -FLT_MAX : al.y + INV_NORM * d[nt][1];
            d[nt][2] = (bB & 1) ? -FLT_MAX : al.x + INV_NORM * d[nt][2];
            d[nt][3] = (bB & 2) ? -FLT_MAX : al.y + INV_NORM * d[nt][3];
        }

        // full row max via quad shuffle (row owned by this warp's quad)
        float mAp = -FLT_MAX, mBp = -FLT_MAX;
#pragma unroll
        for (int nt = 0; nt < 8; nt++) {
            mAp = fmaxf(mAp, fmaxf(d[nt][0], d[nt][1]));
            mBp = fmaxf(mBp, fmaxf(d[nt][2], d[nt][3]));
        }
        mAp = fmaxf(mAp, __shfl_xor_sync(0xffffffffu, mAp, 1));
        mAp = fmaxf(mAp, __shfl_xor_sync(0xffffffffu, mAp, 2));
        mBp = fmaxf(mBp, __shfl_xor_sync(0xffffffffu, mBp, 1));
        mBp = fmaxf(mBp, __shfl_xor_sync(0xffffffffu, mBp, 2));

        const float mnA = fmaxf(stMA, mAp);
        const float mnB = fmaxf(stMB, mBp);
        const float cA = __expf(stMA - mnA);
        const float cB = __expf(stMB - mnB);
        stMA = mnA; stMB = mnB;

        // exp + pack P into A-fragments (registers only)
        uint32_t paA[8], paB[8];
        float sumA = 0.f, sumB = 0.f;
#pragma unroll
        for (int nt = 0; nt < 8; nt++) {
            float p00 = __expf(d[nt][0] - mnA);
            float p01 = __expf(d[nt][1] - mnA);
            float p10 = __expf(d[nt][2] - mnB);
            float p11 = __expf(d[nt][3] - mnB);
            sumA += p00 + p01;
            sumB += p10 + p11;
            __half2 hA = __float22half2_rn(make_float2(p00, p01));
            __half2 hB = __float22half2_rn(make_float2(p10, p11));
            paA[nt] = *(uint32_t*)&hA;
            paB[nt] = *(uint32_t*)&hB;
        }
        sumA += __shfl_xor_sync(0xffffffffu, sumA, 1);
        sumA += __shfl_xor_sync(0xffffffffu, sumA, 2);
        sumB += __shfl_xor_sync(0xffffffffu, sumB, 1);
        sumB += __shfl_xor_sync(0xffffffffu, sumB, 2);
        stLA = stLA * cA + sumA;
        stLB = stLB * cB + sumB;

        // Phase 3: O = O*c + P @ V (warp tile 16x128, A from registers)
#pragma unroll
        for (int nt = 0; nt < 16; nt++) {
            o[nt][0] *= cA; o[nt][1] *= cA;
            o[nt][2] *= cB; o[nt][3] *= cB;
        }
#pragma unroll
        for (int ks = 0; ks < 4; ks++) {
            const uint32_t a0 = paA[2 * ks];
            const uint32_t a1 = paB[2 * ks];
            const uint32_t a2 = paA[2 * ks + 1];
            const uint32_t a3 = paB[2 * ks + 1];
#pragma unroll
            for (int nt = 0; nt < 16; nt++) {
                const int colD = nt * 8 + gid;
                const uint32_t b0 = Vp[colD * 36 + ks * 8 + tig];
                const uint32_t b1 = Vp[colD * 36 + ks * 8 + 4 + tig];
                MMA_F16(o[nt], a0, a1, a2, a3, b0, b1);
            }
        }
    }

    // epilogue: warp-local l, divide, store
    {
        const float lA = 1.0f / stLA;
        const float lB = 1.0f / stLB;
        const int rowA = b * S_LEN + q0 + mrow;
#pragma unroll
        for (int nt = 0; nt < 16; nt++) {
            const int col = head * HEADD + nt * 8 + tig * 2;
            *(__half2*)&ctx[(size_t)rowA * HDIM + col] =
                __float22half2_rn(make_float2(o[nt][0] * lA, o[nt][1] * lA));
            *(__half2*)&ctx[(size_t)(rowA + 8) * HDIM + col] =
                __float22half2_rn(make_float2(o[nt][2] * lB, o[nt][3] * lB));
        }
    }
}

// ---------------------------------------------------------------------------
extern "C" void kernel_launch(void* const* d_in, const int* in_sizes, int n_in,
                              void* d_out, int out_size)
{
    const float* hs    = (const float*)d_in[0];
    const float* resid = (const float*)d_in[1];
    const float* alibi = (const float*)d_in[2];
    const void*  maskp = d_in[3];
    const float* qkv_w = (const float*)d_in[4];
    const float* qkv_b = (const float*)d_in[5];
    const float* dw    = (const float*)d_in[6];
    const float* db    = (const float*)d_in[7];
    float* out = (float*)d_out;

    __half *rw, *rhs, *rw2, *ctxh;
    uint32_t* maskw;
    cudaGetSymbolAddress((void**)&rw,    g_rwh);
    cudaGetSymbolAddress((void**)&rhs,   g_rhsh);
    cudaGetSymbolAddress((void**)&rw2,   g_rw2h);
    cudaGetSymbolAddress((void**)&ctxh,  g_ctxh);
    cudaGetSymbolAddress((void**)&maskw, g_maskw);

    cudaFuncSetAttribute(gemm_f16, cudaFuncAttributeMaxDynamicSharedMemorySize,
                         GEMM_SMEM_BYTES);
    cudaFuncSetAttribute(attn_f16, cudaFuncAttributeMaxDynamicSharedMemorySize,
                         ATTN_SMEM_BYTES);

    k_set_flags<<<1, 1>>>();
    k_detect<<<256, 256>>>((const int*)maskp, in_sizes[3] / 4);
    k_pack_bits<<<256, 256>>>(maskp, maskw, MASK_WORDS);

    // fused f32 -> half converts (qkv_w, hs, dense_w)
    k_cvt3<<<8192, 256>>>(
        (const float4*)qkv_w, (uint2*)rw,  (int)((size_t)QKV_N * HDIM / 4),
        (const float4*)hs,    (uint2*)rhs, (int)((size_t)M_ROWS * HDIM / 4),
        (const float4*)dw,    (uint2*)rw2, (int)((size_t)HDIM * HDIM / 4));

    // QKV projection (fp16 tensor cores) -> g_qkvh (q,k) + g_vth (V^T)
    gemm_f16<<<dim3(QKV_N / 128, M_ROWS / 128), 256, GEMM_SMEM_BYTES>>>(
        rhs, rw, qkv_b, nullptr, nullptr, M_ROWS, QKV_N, HDIM, 1);

    // Flash attention (BQ=128, register-resident P, bit mask) -> g_ctxh
    attn_f16<<<dim3(S_LEN / BQ, BATCH * NHEADS), 256, ATTN_SMEM_BYTES>>>(
        alibi, maskw, ctxh);

    // Output projection + bias + residual (fp16 tensor cores, f32 out)
    gemm_f16<<<dim3(HDIM / 128, M_ROWS / 128), 256, GEMM_SMEM_BYTES>>>(
        ctxh, rw2, db, resid, out, M_ROWS, HDIM, HDIM, 0);
}

// round 14
// speedup vs baseline: 1.0873x; 1.0032x over previous
#include <cuda_runtime.h>
#include <cuda_fp16.h>
#include <cfloat>
#include <cstdint>

// Problem constants
#define S_LEN   2048
#define BATCH   2
#define HDIM    4096
#define NHEADS  32
#define HEADD   128
#define M_ROWS  4096            // B*S
#define QKV_N   12288           // 3*H
#define INV_NORM 0.08838834764831845f   // 1/sqrt(128)
#define MASK_WORDS (BATCH * S_LEN * S_LEN / 32)   // 262144 u32 = 1MB

// Scratch (allocation-free rule: __device__ globals). All half-precision.
__device__ __half g_qkvh[(size_t)M_ROWS * 8192];        // [row][head][{q,k}][128]
__device__ __half g_vth [(size_t)64 * 128 * 2048];      // [b*NH+h][d][s] (V^T)
__device__ __half g_rwh [(size_t)QKV_N * HDIM];         // qkv_w half
__device__ __half g_rhsh[(size_t)M_ROWS * HDIM];        // hs half
__device__ __half g_rw2h[(size_t)HDIM * HDIM];          // dense_w half
__device__ __half g_ctxh[(size_t)M_ROWS * HDIM];        // ctx half
__device__ uint32_t g_maskw[MASK_WORDS];                // bit-packed mask
__device__ int   g_all_int01;
__device__ int   g_all_f01;

// ---------------------------------------------------------------------------
__global__ void k_detect(const int* __restrict__ w, int n) {
    for (int i = blockIdx.x * blockDim.x + threadIdx.x; i < n;
         i += gridDim.x * blockDim.x) {
        int v = w[i];
        if ((unsigned)v > 1u) g_all_int01 = 0;
        float f = __int_as_float(v);
        if (!(f == 0.0f || f == 1.0f)) g_all_f01 = 0;
    }
}

// Pack mask (any wire dtype) -> 1 bit per element
__global__ void k_pack_bits(const void* __restrict__ in,
                            uint32_t* __restrict__ out, int nwords) {
    const int mtype = g_all_int01 ? 1 : (g_all_f01 ? 2 : 0);
    for (int w = blockIdx.x * blockDim.x + threadIdx.x; w < nwords;
         w += gridDim.x * blockDim.x) {
        uint32_t bits = 0;
        if (mtype == 1) {
            const int4* p = (const int4*)in + (size_t)w * 8;
#pragma unroll
            for (int j = 0; j < 8; j++) {
                int4 v = p[j];
                bits |= (v.x != 0 ? 1u : 0u) << (j * 4 + 0);
                bits |= (v.y != 0 ? 1u : 0u) << (j * 4 + 1);
                bits |= (v.z != 0 ? 1u : 0u) << (j * 4 + 2);
                bits |= (v.w != 0 ? 1u : 0u) << (j * 4 + 3);
            }
        } else if (mtype == 2) {
            const float4* p = (const float4*)in + (size_t)w * 8;
#pragma unroll
            for (int j = 0; j < 8; j++) {
                float4 v = p[j];
                bits |= (v.x != 0.f ? 1u : 0u) << (j * 4 + 0);
                bits |= (v.y != 0.f ? 1u : 0u) << (j * 4 + 1);
                bits |= (v.z != 0.f ? 1u : 0u) << (j * 4 + 2);
                bits |= (v.w != 0.f ? 1u : 0u) << (j * 4 + 3);
            }
        } else {
            const uint4* p = (const uint4*)in + (size_t)w * 2;
#pragma unroll
            for (int j = 0; j < 2; j++) {
                uint4 v = p[j];
                const uint32_t ws[4] = {v.x, v.y, v.z, v.w};
#pragma unroll
                for (int q = 0; q < 4; q++)
#pragma unroll
                    for (int bb = 0; bb < 4; bb++)
                        bits |= (((ws[q] >> (bb * 8)) & 0xFFu) != 0 ? 1u : 0u)
                                << (j * 16 + q * 4 + bb);
            }
        }
        out[w] = bits;
    }
}

// Fused f32 -> packed half2 conversion; block-range segmented (no per-iter branch)
__global__ void k_cvt3(const float4* __restrict__ i1, uint2* __restrict__ o1, int n1,
                       const float4* __restrict__ i2, uint2* __restrict__ o2, int n2,
                       const float4* __restrict__ i3, uint2* __restrict__ o3, int n3,
                       int blks1, int blks2)
{
    const float4* src; uint2* dst; int n; int blk0; int nblks;
    if ((int)blockIdx.x < blks1) {
        src = i1; dst = o1; n = n1; blk0 = 0; nblks = blks1;
    } else if ((int)blockIdx.x < blks1 + blks2) {
        src = i2; dst = o2; n = n2; blk0 = blks1; nblks = blks2;
    } else {
        src = i3; dst = o3; n = n3; blk0 = blks1 + blks2;
        nblks = gridDim.x - blks1 - blks2;
    }
    const int stride = nblks * blockDim.x;
    for (int i = ((int)blockIdx.x - blk0) * blockDim.x + threadIdx.x; i < n;
         i += stride) {
        float4 v = src[i];
        __half2 lo = __float22half2_rn(make_float2(v.x, v.y));
        __half2 hi = __float22half2_rn(make_float2(v.z, v.w));
        uint2 o;
        o.x = *(uint32_t*)&lo;
        o.y = *(uint32_t*)&hi;
        dst[i] = o;
    }
}

// ---------------------------------------------------------------------------
// cp.async helpers
// ---------------------------------------------------------------------------
__device__ __forceinline__ void cp16(void* dst, const void* src) {
    uint32_t d = (uint32_t)__cvta_generic_to_shared(dst);
    asm volatile("cp.async.cg.shared.global [%0], [%1], 16;" :: "r"(d), "l"(src));
}
#define CP_COMMIT()  asm volatile("cp.async.commit_group;")
#define CP_WAIT(n)   asm volatile("cp.async.wait_group %0;" :: "n"(n))

// fp16 MMA m16n8k16, f32 accumulate
#define MMA_F16(D, a0, a1, a2, a3, b0, b1)                                    \
    asm volatile(                                                             \
        "mma.sync.aligned.m16n8k16.row.col.f32.f16.f16.f32 "                  \
        "{%0,%1,%2,%3}, {%4,%5,%6,%7}, {%8,%9}, {%0,%1,%2,%3};"               \
        : "+f"(D[0]), "+f"(D[1]), "+f"(D[2]), "+f"(D[3])                      \
        : "r"(a0), "r"(a1), "r"(a2), "r"(a3), "r"(b0), "r"(b1))

// ---------------------------------------------------------------------------
// FP16 GEMM (NT), 3-stage cp.async pipeline.  (R9/R13 proven version)
// Block 128x128, K-tile 64 halves, 256 threads (8 warps 4x2), warp tile 32x64.
// mode 0: f32 out C = acc + bias + resid
// mode 1: qkv split -> g_qkvh (q,k packed half) + g_vth (V^T scatter stores)
// ---------------------------------------------------------------------------
#define GBK 64                       // K-tile in halves
#define GPAD 36                      // row stride in uint32 (144B)
#define GROWB 144                    // row stride bytes
#define GSTG_B (256 * GROWB)         // 36864 B per stage (A 128 rows + B 128)
#define GNSTG 3
#define GEMM_SMEM_BYTES (GNSTG * GSTG_B)

__global__ __launch_bounds__(256, 2)
void gemm_f16(const __half* __restrict__ A, const __half* __restrict__ W,
              const float* __restrict__ bias, const float* __restrict__ resid,
              float* __restrict__ C, int M, int N, int K, int mode)
{
    extern __shared__ unsigned char gsmb[];

    const int t    = threadIdx.x;
    const int warp = t >> 5;
    const int lane = t & 31;
    const int gid  = lane >> 2;
    const int tig  = lane & 3;
    const int wm   = (warp >> 1) * 32;
    const int wn   = (warp & 1) * 64;

    const int bm = blockIdx.y * 128;
    const int bn = blockIdx.x * 128;
    const int NT = K / GBK;

    float d[2][8][4];
#pragma unroll
    for (int i = 0; i < 2; i++)
#pragma unroll
        for (int j = 0; j < 8; j++)
#pragma unroll
            for (int c = 0; c < 4; c++) d[i][j][c] = 0.f;

    // loader: 256 rows x 8 chunks (16B) = 2048 tasks, 8 per thread
    auto load_stage = [&](int st, int kk0) {
        unsigned char* stg = gsmb + st * GSTG_B;
#pragma unroll
        for (int i = 0; i < 8; i++) {
            const int e = i * 256 + t;
            const int r = e >> 3, c = e & 7;
            const __half* src = (r < 128)
                ? A + (size_t)(bm + r) * K + kk0 + c * 8
                : W + (size_t)(bn + r - 128) * K + kk0 + c * 8;
            cp16(stg + r * GROWB + c * 16, src);
        }
    };

    load_stage(0, 0);    CP_COMMIT();
    load_stage(1, GBK);  CP_COMMIT();

    for (int kt = 0; kt < NT; kt++) {
        const int s = kt % GNSTG;
        CP_WAIT(1);
        __syncthreads();
        if (kt + 2 < NT) load_stage((kt + 2) % GNSTG, (kt + 2) * GBK);
        CP_COMMIT();

        const uint32_t* As = (const uint32_t*)(gsmb + s * GSTG_B);
        const uint32_t* Ws = As + 128 * GPAD;

#pragma unroll
        for (int ks = 0; ks < 4; ks++) {
            uint32_t a[2][4];
#pragma unroll
            for (int mt = 0; mt < 2; mt++) {
                const int r = wm + mt * 16 + gid;
                a[mt][0] = As[r * GPAD + ks * 8 + tig];
                a[mt][1] = As[(r + 8) * GPAD + ks * 8 + tig];
                a[mt][2] = As[r * GPAD + ks * 8 + 4 + tig];
                a[mt][3] = As[(r + 8) * GPAD + ks * 8 + 4 + tig];
            }
            uint32_t b[8][2];
#pragma unroll
            for (int nt = 0; nt < 8; nt++) {
                const int r = wn + nt * 8 + gid;
                b[nt][0] = Ws[r * GPAD + ks * 8 + tig];
                b[nt][1] = Ws[r * GPAD + ks * 8 + 4 + tig];
            }
#pragma unroll
            for (int mt = 0; mt < 2; mt++)
#pragma unroll
                for (int nt = 0; nt < 8; nt++)
                    MMA_F16(d[mt][nt], a[mt][0], a[mt][1], a[mt][2], a[mt][3],
                            b[nt][0], b[nt][1]);
        }
    }

    // Epilogue (scatter version — proven)
#pragma unroll
    for (int mt = 0; mt < 2; mt++) {
        const int r0 = bm + wm + mt * 16 + gid;
#pragma unroll
        for (int nt = 0; nt < 8; nt++) {
            const int col = bn + wn + nt * 8 + tig * 2;
            const float b0 = bias[col], b1 = bias[col + 1];
            float v00 = d[mt][nt][0] + b0, v01 = d[mt][nt][1] + b1;
            float v10 = d[mt][nt][2] + b0, v11 = d[mt][nt][3] + b1;
            if (mode == 0) {
                size_t i0 = (size_t)r0 * N + col;
                size_t i1 = (size_t)(r0 + 8) * N + col;
                const float2 rr0 = *(const float2*)(resid + i0);
                const float2 rr1 = *(const float2*)(resid + i1);
                *(float2*)(C + i0) = make_float2(v00 + rr0.x, v01 + rr0.y);
                *(float2*)(C + i1) = make_float2(v10 + rr1.x, v11 + rr1.y);
            } else {
                const int head = col / 384;
                const int rem  = col - head * 384;
                const int part = rem >> 7;
                const int dd   = rem & 127;
                if (part < 2) {
                    size_t base = (size_t)r0 * 8192 + head * 256 + part * 128 + dd;
                    *(__half2*)&g_qkvh[base] =
                        __float22half2_rn(make_float2(v00, v01));
                    *(__half2*)&g_qkvh[base + (size_t)8 * 8192] =
                        __float22half2_rn(make_float2(v10, v11));
                } else {
                    const int bb = r0 >> 11, s0 = r0 & 2047;
                    size_t vb = ((size_t)(bb * 32 + head) * 128 + dd) * 2048;
                    g_vth[vb + s0]            = __float2half_rn(v00);
                    g_vth[vb + 2048 + s0]     = __float2half_rn(v01);
                    g_vth[vb + s0 + 8]        = __float2half_rn(v10);
                    g_vth[vb + 2048 + s0 + 8] = __float2half_rn(v11);
                }
            }
        }
    }
}

// ---------------------------------------------------------------------------
// FP16 flash attention, BQ=128: each warp owns 16 full rows. P stays in
// registers (C-fragment == A-fragment after half2 pack). Softmax is pure
// quad-shuffle. One __syncthreads per KV tile. Bit-packed mask (L2-resident).
// ---------------------------------------------------------------------------
#define BQ 128
#define BKV 64
#define ATTN_NT (S_LEN / BKV)

#define SQ_OFF  0
#define SK_OFF  (128 * 272)                       // 34816
#define SVT_OFF (SK_OFF + 2 * 64 * 272)           // 69632
#define ATTN_SMEM_BYTES (SVT_OFF + 2 * 128 * 144) // 106496

__global__ __launch_bounds__(256, 1)
void attn_f16(const float* __restrict__ alibi,
              const uint32_t* __restrict__ maskw,
              __half* __restrict__ ctx)
{
    extern __shared__ unsigned char smem[];

    const int t    = threadIdx.x;
    const int warp = t >> 5, lane = t & 31;
    const int gid  = lane >> 2, tig = lane & 3;
    const int hh   = blockIdx.y;
    const int b    = hh / NHEADS;
    const int head = hh % NHEADS;
    const int q0   = blockIdx.x * BQ;
    const int mrow = warp * 16 + gid;             // local row (and +8)

    const uint32_t* mw = maskw + (size_t)b * (S_LEN * S_LEN / 32);

    // Q tile: 128 rows x 16 chunks (256B of halves per row)
    {
        const __half* qsrc = g_qkvh + (size_t)(b * S_LEN + q0) * 8192 + head * 256;
        for (int e = t; e < 2048; e += 256) {
            const int r = e >> 4, c = e & 15;
            cp16(smem + SQ_OFF + r * 272 + c * 16, qsrc + (size_t)r * 8192 + c * 8);
        }
    }

    const __half* ksrc0 = g_qkvh + (size_t)b * S_LEN * 8192 + head * 256 + 128;
    const __half* vsrc0 = g_vth + (size_t)hh * 128 * 2048;

    auto load_kv = [&](int st, int k0) {
        unsigned char* sK = smem + SK_OFF + st * (64 * 272);
        unsigned char* sV = smem + SVT_OFF + st * (128 * 144);
        for (int e = t; e < 2048; e += 256) {
            if (e < 1024) {   // K: 64 rows x 16 chunks
                const int r = e >> 4, c = e & 15;
                cp16(sK + r * 272 + c * 16,
                     ksrc0 + (size_t)(k0 + r) * 8192 + c * 8);
            } else {          // V^T: 128 d-rows x 8 chunks (128B per row)
                const int e2 = e - 1024;
                const int r = e2 >> 3, c = e2 & 7;
                cp16(sV + r * 144 + c * 16,
                     vsrc0 + (size_t)r * 2048 + k0 + c * 8);
            }
        }
    };

    load_kv(0, 0);
    CP_COMMIT();

    float o[16][4];
#pragma unroll
    for (int nt = 0; nt < 16; nt++)
#pragma unroll
        for (int c = 0; c < 4; c++) o[nt][c] = 0.f;

    // softmax state in registers; rows fully warp-owned
    float stMA = -FLT_MAX, stMB = -FLT_MAX;
    float stLA = 0.f, stLB = 0.f;

    for (int kt = 0; kt < ATTN_NT; kt++) {
        const int s  = kt & 1;
        const int k0 = kt * BKV;
        CP_WAIT(0);
        __syncthreads();                          // buffers rotated
        if (kt + 1 < ATTN_NT) load_kv(s ^ 1, k0 + BKV);
        CP_COMMIT();

        const uint32_t* Qp = (const uint32_t*)(smem + SQ_OFF);
        const uint32_t* Kp = (const uint32_t*)(smem + SK_OFF + s * (64 * 272));
        const uint32_t* Vp = (const uint32_t*)(smem + SVT_OFF + s * (128 * 144));

        // Phase 1: S = Q K^T, warp tile 16x64 (8 nt x 8 ks MMAs)
        float d[8][4];
#pragma unroll
        for (int nt = 0; nt < 8; nt++)
#pragma unroll
            for (int c = 0; c < 4; c++) d[nt][c] = 0.f;

#pragma unroll
        for (int ks = 0; ks < 8; ks++) {
            const uint32_t a0 = Qp[mrow * 68 + ks * 8 + tig];
            const uint32_t a1 = Qp[(mrow + 8) * 68 + ks * 8 + tig];
            const uint32_t a2 = Qp[mrow * 68 + ks * 8 + 4 + tig];
            const uint32_t a3 = Qp[(mrow + 8) * 68 + ks * 8 + 4 + tig];
#pragma unroll
            for (int nt = 0; nt < 8; nt++) {
                const int key = nt * 8 + gid;
                const uint32_t b0 = Kp[key * 68 + ks * 8 + tig];
                const uint32_t b1 = Kp[key * 68 + ks * 8 + 4 + tig];
                MMA_F16(d[nt], a0, a1, a2, a3, b0, b1);
            }
        }

        // alibi + bit-packed mask in registers (cols nt*8+2tig over 0..63)
        const int qrA = q0 + mrow, qrB = qrA + 8;
        const uint2 wA = *(const uint2*)&mw[qrA * 64 + (k0 >> 5)];
        const uint2 wB = *(const uint2*)&mw[qrB * 64 + (k0 >> 5)];
#pragma unroll
        for (int nt = 0; nt < 8; nt++) {
            const int colL = nt * 8 + tig * 2;
            const int kc   = k0 + colL;
            const float2 al = *(const float2*)(alibi + (size_t)hh * S_LEN + kc);
            const int sh = (nt & 3) * 8 + tig * 2;
            const uint32_t bA = ((nt < 4) ? wA.x : wA.y) >> sh;
            const uint32_t bB = ((nt < 4) ? wB.x : wB.y) >> sh;
            d[nt][0] = (bA & 1) ? -FLT_MAX : al.x + INV_NORM * d[nt][0];
            d[nt][1] = (bA & 2) ? -FLT_MAX : al.y + INV_NORM * d[nt][1];
            d[nt][2] = (bB & 1) ? -FLT_MAX : al.x + INV_NORM * d[nt][2];
            d[nt][3] = (bB & 2) ? -FLT_MAX : al.y + INV_NORM * d[nt][3];
        }

        // full row max via quad shuffle (row owned by this warp's quad)
        float mAp = -FLT_MAX, mBp = -FLT_MAX;
#pragma unroll
        for (int nt = 0; nt < 8; nt++) {
            mAp = fmaxf(mAp, fmaxf(d[nt][0], d[nt][1]));
            mBp = fmaxf(mBp, fmaxf(d[nt][2], d[nt][3]));
        }
        mAp = fmaxf(mAp, __shfl_xor_sync(0xffffffffu, mAp, 1));
        mAp = fmaxf(mAp, __shfl_xor_sync(0xffffffffu, mAp, 2));
        mBp = fmaxf(mBp, __shfl_xor_sync(0xffffffffu, mBp, 1));
        mBp = fmaxf(mBp, __shfl_xor_sync(0xffffffffu, mBp, 2));

        const float mnA = fmaxf(stMA, mAp);
        const float mnB = fmaxf(stMB, mBp);
        const float cA = __expf(stMA - mnA);
        const float cB = __expf(stMB - mnB);
        stMA = mnA; stMB = mnB;

        // exp + pack P into A-fragments (registers only)
        uint32_t paA[8], paB[8];
        float sumA = 0.f, sumB = 0.f;
#pragma unroll
        for (int nt = 0; nt < 8; nt++) {
            float p00 = __expf(d[nt][0] - mnA);
            float p01 = __expf(d[nt][1] - mnA);
            float p10 = __expf(d[nt][2] - mnB);
            float p11 = __expf(d[nt][3] - mnB);
            sumA += p00 + p01;
            sumB += p10 + p11;
            __half2 hA = __float22half2_rn(make_float2(p00, p01));
            __half2 hB = __float22half2_rn(make_float2(p10, p11));
            paA[nt] = *(uint32_t*)&hA;
            paB[nt] = *(uint32_t*)&hB;
        }
        sumA += __shfl_xor_sync(0xffffffffu, sumA, 1);
        sumA += __shfl_xor_sync(0xffffffffu, sumA, 2);
        sumB += __shfl_xor_sync(0xffffffffu, sumB, 1);
        sumB += __shfl_xor_sync(0xffffffffu, sumB, 2);
        stLA = stLA * cA + sumA;
        stLB = stLB * cB + sumB;

        // Phase 3: O = O*c + P @ V (warp tile 16x128, A from registers)
#pragma unroll
        for (int nt = 0; nt < 16; nt++) {
            o[nt][0] *= cA; o[nt][1] *= cA;
            o[nt][2] *= cB; o[nt][3] *= cB;
        }
#pragma unroll
        for (int ks = 0; ks < 4; ks++) {
            const uint32_t a0 = paA[2 * ks];
            const uint32_t a1 = paB[2 * ks];
            const uint32_t a2 = paA[2 * ks + 1];
            const uint32_t a3 = paB[2 * ks + 1];
#pragma unroll
            for (int nt = 0; nt < 16; nt++) {
                const int colD = nt * 8 + gid;
                const uint32_t b0 = Vp[colD * 36 + ks * 8 + tig];
                const uint32_t b1 = Vp[colD * 36 + ks * 8 + 4 + tig];
                MMA_F16(o[nt], a0, a1, a2, a3, b0, b1);
            }
        }
    }

    // epilogue: warp-local l, divide, store
    {
        const float lA = 1.0f / stLA;
        const float lB = 1.0f / stLB;
        const int rowA = b * S_LEN + q0 + mrow;
#pragma unroll
        for (int nt = 0; nt < 16; nt++) {
            const int col = head * HEADD + nt * 8 + tig * 2;
            *(__half2*)&ctx[(size_t)rowA * HDIM + col] =
                __float22half2_rn(make_float2(o[nt][0] * lA, o[nt][1] * lA));
            *(__half2*)&ctx[(size_t)(rowA + 8) * HDIM + col] =
                __float22half2_rn(make_float2(o[nt][2] * lB, o[nt][3] * lB));
        }
    }
}

// ---------------------------------------------------------------------------
extern "C" void kernel_launch(void* const* d_in, const int* in_sizes, int n_in,
                              void* d_out, int out_size)
{
    const float* hs    = (const float*)d_in[0];
    const float* resid = (const float*)d_in[1];
    const float* alibi = (const float*)d_in[2];
    const void*  maskp = d_in[3];
    const float* qkv_w = (const float*)d_in[4];
    const float* qkv_b = (const float*)d_in[5];
    const float* dw    = (const float*)d_in[6];
    const float* db    = (const float*)d_in[7];
    float* out = (float*)d_out;

    __half *rw, *rhs, *rw2, *ctxh;
    uint32_t* maskw;
    int *fi, *ff;
    cudaGetSymbolAddress((void**)&rw,    g_rwh);
    cudaGetSymbolAddress((void**)&rhs,   g_rhsh);
    cudaGetSymbolAddress((void**)&rw2,   g_rw2h);
    cudaGetSymbolAddress((void**)&ctxh,  g_ctxh);
    cudaGetSymbolAddress((void**)&maskw, g_maskw);
    cudaGetSymbolAddress((void**)&fi,    g_all_int01);
    cudaGetSymbolAddress((void**)&ff,    g_all_f01);

    cudaFuncSetAttribute(gemm_f16, cudaFuncAttributeMaxDynamicSharedMemorySize,
                         GEMM_SMEM_BYTES);
    cudaFuncSetAttribute(attn_f16, cudaFuncAttributeMaxDynamicSharedMemorySize,
                         ATTN_SMEM_BYTES);

    // flag init via async memset (graph-capturable, nonzero == true)
    cudaMemsetAsync(fi, 1, sizeof(int));
    cudaMemsetAsync(ff, 1, sizeof(int));
    k_detect<<<256, 256>>>((const int*)maskp, in_sizes[3] / 4);
    k_pack_bits<<<512, 256>>>(maskp, maskw, MASK_WORDS);

    // fused f32 -> half converts (qkv_w, hs, dense_w), block-range segmented
    {
        const int n1 = (int)((size_t)QKV_N * HDIM / 4);   // 12582912
        const int n2 = (int)((size_t)M_ROWS * HDIM / 4);  // 4194304
        const int n3 = (int)((size_t)HDIM * HDIM / 4);    // 4194304
        const int total_blks = 8192;
        // proportional block split (n1:n2:n3 = 3:1:1)
        const int blks1 = 4916, blks2 = 1638;             // rest = 1638
        k_cvt3<<<total_blks, 256>>>(
            (const float4*)qkv_w, (uint2*)rw,  n1,
            (const float4*)hs,    (uint2*)rhs, n2,
            (const float4*)dw,    (uint2*)rw2, n3,
            blks1, blks2);
    }

    // QKV projection (fp16 tensor cores) -> g_qkvh (q,k) + g_vth (V^T)
    gemm_f16<<<dim3(QKV_N / 128, M_ROWS / 128), 256, GEMM_SMEM_BYTES>>>(
        rhs, rw, qkv_b, nullptr, nullptr, M_ROWS, QKV_N, HDIM, 1);

    // Flash attention (BQ=128, register-resident P, bit mask) -> g_ctxh
    attn_f16<<<dim3(S_LEN / BQ, BATCH * NHEADS), 256, ATTN_SMEM_BYTES>>>(
        alibi, maskw, ctxh);

    // Output projection + bias + residual (fp16 tensor cores, f32 out)
    gemm_f16<<<dim3(HDIM / 128, M_ROWS / 128), 256, GEMM_SMEM_BYTES>>>(
        ctxh, rw2, db, resid, out, M_ROWS, HDIM, HDIM, 0);
}

// round 15
// speedup vs baseline: 1.0895x; 1.0020x over previous
#include <cuda_runtime.h>
#include <cuda_fp16.h>
#include <cfloat>
#include <cstdint>

// Problem constants
#define S_LEN   2048
#define BATCH   2
#define HDIM    4096
#define NHEADS  32
#define HEADD   128
#define M_ROWS  4096            // B*S
#define QKV_N   12288           // 3*H
#define INV_NORM 0.08838834764831845f   // 1/sqrt(128)
#define MASK_WORDS (BATCH * S_LEN * S_LEN / 32)   // 262144 u32 = 1MB

// Scratch (allocation-free rule: __device__ globals). All half-precision.
__device__ __half g_qkvh[(size_t)M_ROWS * 8192];        // [row][head][{q,k}][128]
__device__ __half g_vth [(size_t)64 * 128 * 2048];      // [b*NH+h][d][s] (V^T)
__device__ __half g_rwh [(size_t)QKV_N * HDIM];         // qkv_w half
__device__ __half g_rhsh[(size_t)M_ROWS * HDIM];        // hs half
__device__ __half g_rw2h[(size_t)HDIM * HDIM];          // dense_w half
__device__ __half g_ctxh[(size_t)M_ROWS * HDIM];        // ctx half
__device__ uint32_t g_maskw[MASK_WORDS];                // bit-packed mask
__device__ int   g_all_int01;
__device__ int   g_all_f01;

// ---------------------------------------------------------------------------
__global__ void k_detect(const int* __restrict__ w, int n) {
    for (int i = blockIdx.x * blockDim.x + threadIdx.x; i < n;
         i += gridDim.x * blockDim.x) {
        int v = w[i];
        if ((unsigned)v > 1u) g_all_int01 = 0;
        float f = __int_as_float(v);
        if (!(f == 0.0f || f == 1.0f)) g_all_f01 = 0;
    }
}

// Pack mask (any wire dtype) -> 1 bit per element
__global__ void k_pack_bits(const void* __restrict__ in,
                            uint32_t* __restrict__ out, int nwords) {
    const int mtype = g_all_int01 ? 1 : (g_all_f01 ? 2 : 0);
    for (int w = blockIdx.x * blockDim.x + threadIdx.x; w < nwords;
         w += gridDim.x * blockDim.x) {
        uint32_t bits = 0;
        if (mtype == 1) {
            const int4* p = (const int4*)in + (size_t)w * 8;
#pragma unroll
            for (int j = 0; j < 8; j++) {
                int4 v = p[j];
                bits |= (v.x != 0 ? 1u : 0u) << (j * 4 + 0);
                bits |= (v.y != 0 ? 1u : 0u) << (j * 4 + 1);
                bits |= (v.z != 0 ? 1u : 0u) << (j * 4 + 2);
                bits |= (v.w != 0 ? 1u : 0u) << (j * 4 + 3);
            }
        } else if (mtype == 2) {
            const float4* p = (const float4*)in + (size_t)w * 8;
#pragma unroll
            for (int j = 0; j < 8; j++) {
                float4 v = p[j];
                bits |= (v.x != 0.f ? 1u : 0u) << (j * 4 + 0);
                bits |= (v.y != 0.f ? 1u : 0u) << (j * 4 + 1);
                bits |= (v.z != 0.f ? 1u : 0u) << (j * 4 + 2);
                bits |= (v.w != 0.f ? 1u : 0u) << (j * 4 + 3);
            }
        } else {
            const uint4* p = (const uint4*)in + (size_t)w * 2;
#pragma unroll
            for (int j = 0; j < 2; j++) {
                uint4 v = p[j];
                const uint32_t ws[4] = {v.x, v.y, v.z, v.w};
#pragma unroll
                for (int q = 0; q < 4; q++)
#pragma unroll
                    for (int bb = 0; bb < 4; bb++)
                        bits |= (((ws[q] >> (bb * 8)) & 0xFFu) != 0 ? 1u : 0u)
                                << (j * 16 + q * 4 + bb);
            }
        }
        out[w] = bits;
    }
}

// Fused f32 -> packed half2 conversion; block-range segmented (no per-iter branch)
__global__ void k_cvt3(const float4* __restrict__ i1, uint2* __restrict__ o1, int n1,
                       const float4* __restrict__ i2, uint2* __restrict__ o2, int n2,
                       const float4* __restrict__ i3, uint2* __restrict__ o3, int n3,
                       int blks1, int blks2)
{
    const float4* src; uint2* dst; int n; int blk0; int nblks;
    if ((int)blockIdx.x < blks1) {
        src = i1; dst = o1; n = n1; blk0 = 0; nblks = blks1;
    } else if ((int)blockIdx.x < blks1 + blks2) {
        src = i2; dst = o2; n = n2; blk0 = blks1; nblks = blks2;
    } else {
        src = i3; dst = o3; n = n3; blk0 = blks1 + blks2;
        nblks = gridDim.x - blks1 - blks2;
    }
    const int stride = nblks * blockDim.x;
    for (int i = ((int)blockIdx.x - blk0) * blockDim.x + threadIdx.x; i < n;
         i += stride) {
        float4 v = src[i];
        __half2 lo = __float22half2_rn(make_float2(v.x, v.y));
        __half2 hi = __float22half2_rn(make_float2(v.z, v.w));
        uint2 o;
        o.x = *(uint32_t*)&lo;
        o.y = *(uint32_t*)&hi;
        dst[i] = o;
    }
}

// ---------------------------------------------------------------------------
// cp.async helpers
// ---------------------------------------------------------------------------
__device__ __forceinline__ void cp16(void* dst, const void* src) {
    uint32_t d = (uint32_t)__cvta_generic_to_shared(dst);
    asm volatile("cp.async.cg.shared.global [%0], [%1], 16;" :: "r"(d), "l"(src));
}
#define CP_COMMIT()  asm volatile("cp.async.commit_group;")
#define CP_WAIT(n)   asm volatile("cp.async.wait_group %0;" :: "n"(n))

// fp16 MMA m16n8k16, f32 accumulate
#define MMA_F16(D, a0, a1, a2, a3, b0, b1)                                    \
    asm volatile(                                                             \
        "mma.sync.aligned.m16n8k16.row.col.f32.f16.f16.f32 "                  \
        "{%0,%1,%2,%3}, {%4,%5,%6,%7}, {%8,%9}, {%0,%1,%2,%3};"               \
        : "+f"(D[0]), "+f"(D[1]), "+f"(D[2]), "+f"(D[3])                      \
        : "r"(a0), "r"(a1), "r"(a2), "r"(a3), "r"(b0), "r"(b1))

// ---------------------------------------------------------------------------
// FP16 GEMM (NT), 3-stage cp.async pipeline.  (R9/R13 proven version)
// Block 128x128, K-tile 64 halves, 256 threads (8 warps 4x2), warp tile 32x64.
// mode 0: f32 out C = acc + bias + resid
// mode 1: qkv split -> g_qkvh (q,k packed half) + g_vth (V^T scatter stores)
// ---------------------------------------------------------------------------
#define GBK 64                       // K-tile in halves
#define GPAD 36                      // row stride in uint32 (144B)
#define GROWB 144                    // row stride bytes
#define GSTG_B (256 * GROWB)         // 36864 B per stage (A 128 rows + B 128)
#define GNSTG 3
#define GEMM_SMEM_BYTES (GNSTG * GSTG_B)

__global__ __launch_bounds__(256, 2)
void gemm_f16(const __half* __restrict__ A, const __half* __restrict__ W,
              const float* __restrict__ bias, const float* __restrict__ resid,
              float* __restrict__ C, int M, int N, int K, int mode)
{
    extern __shared__ unsigned char gsmb[];

    const int t    = threadIdx.x;
    const int warp = t >> 5;
    const int lane = t & 31;
    const int gid  = lane >> 2;
    const int tig  = lane & 3;
    const int wm   = (warp >> 1) * 32;
    const int wn   = (warp & 1) * 64;

    const int bm = blockIdx.y * 128;
    const int bn = blockIdx.x * 128;
    const int NT = K / GBK;

    float d[2][8][4];
#pragma unroll
    for (int i = 0; i < 2; i++)
#pragma unroll
        for (int j = 0; j < 8; j++)
#pragma unroll
            for (int c = 0; c < 4; c++) d[i][j][c] = 0.f;

    // loader: 256 rows x 8 chunks (16B) = 2048 tasks, 8 per thread
    auto load_stage = [&](int st, int kk0) {
        unsigned char* stg = gsmb + st * GSTG_B;
#pragma unroll
        for (int i = 0; i < 8; i++) {
            const int e = i * 256 + t;
            const int r = e >> 3, c = e & 7;
            const __half* src = (r < 128)
                ? A + (size_t)(bm + r) * K + kk0 + c * 8
                : W + (size_t)(bn + r - 128) * K + kk0 + c * 8;
            cp16(stg + r * GROWB + c * 16, src);
        }
    };

    load_stage(0, 0);    CP_COMMIT();
    load_stage(1, GBK);  CP_COMMIT();

    for (int kt = 0; kt < NT; kt++) {
        const int s = kt % GNSTG;
        CP_WAIT(1);
        __syncthreads();
        if (kt + 2 < NT) load_stage((kt + 2) % GNSTG, (kt + 2) * GBK);
        CP_COMMIT();

        const uint32_t* As = (const uint32_t*)(gsmb + s * GSTG_B);
        const uint32_t* Ws = As + 128 * GPAD;

#pragma unroll
        for (int ks = 0; ks < 4; ks++) {
            uint32_t a[2][4];
#pragma unroll
            for (int mt = 0; mt < 2; mt++) {
                const int r = wm + mt * 16 + gid;
                a[mt][0] = As[r * GPAD + ks * 8 + tig];
                a[mt][1] = As[(r + 8) * GPAD + ks * 8 + tig];
                a[mt][2] = As[r * GPAD + ks * 8 + 4 + tig];
                a[mt][3] = As[(r + 8) * GPAD + ks * 8 + 4 + tig];
            }
            uint32_t b[8][2];
#pragma unroll
            for (int nt = 0; nt < 8; nt++) {
                const int r = wn + nt * 8 + gid;
                b[nt][0] = Ws[r * GPAD + ks * 8 + tig];
                b[nt][1] = Ws[r * GPAD + ks * 8 + 4 + tig];
            }
#pragma unroll
            for (int mt = 0; mt < 2; mt++)
#pragma unroll
                for (int nt = 0; nt < 8; nt++)
                    MMA_F16(d[mt][nt], a[mt][0], a[mt][1], a[mt][2], a[mt][3],
                            b[nt][0], b[nt][1]);
        }
    }

    // Epilogue (scatter version — proven)
#pragma unroll
    for (int mt = 0; mt < 2; mt++) {
        const int r0 = bm + wm + mt * 16 + gid;
#pragma unroll
        for (int nt = 0; nt < 8; nt++) {
            const int col = bn + wn + nt * 8 + tig * 2;
            const float b0 = bias[col], b1 = bias[col + 1];
            float v00 = d[mt][nt][0] + b0, v01 = d[mt][nt][1] + b1;
            float v10 = d[mt][nt][2] + b0, v11 = d[mt][nt][3] + b1;
            if (mode == 0) {
                size_t i0 = (size_t)r0 * N + col;
                size_t i1 = (size_t)(r0 + 8) * N + col;
                const float2 rr0 = *(const float2*)(resid + i0);
                const float2 rr1 = *(const float2*)(resid + i1);
                *(float2*)(C + i0) = make_float2(v00 + rr0.x, v01 + rr0.y);
                *(float2*)(C + i1) = make_float2(v10 + rr1.x, v11 + rr1.y);
            } else {
                const int head = col / 384;
                const int rem  = col - head * 384;
                const int part = rem >> 7;
                const int dd   = rem & 127;
                if (part < 2) {
                    size_t base = (size_t)r0 * 8192 + head * 256 + part * 128 + dd;
                    *(__half2*)&g_qkvh[base] =
                        __float22half2_rn(make_float2(v00, v01));
                    *(__half2*)&g_qkvh[base + (size_t)8 * 8192] =
                        __float22half2_rn(make_float2(v10, v11));
                } else {
                    const int bb = r0 >> 11, s0 = r0 & 2047;
                    size_t vb = ((size_t)(bb * 32 + head) * 128 + dd) * 2048;
                    g_vth[vb + s0]            = __float2half_rn(v00);
                    g_vth[vb + 2048 + s0]     = __float2half_rn(v01);
                    g_vth[vb + s0 + 8]        = __float2half_rn(v10);
                    g_vth[vb + 2048 + s0 + 8] = __float2half_rn(v11);
                }
            }
        }
    }
}

// ---------------------------------------------------------------------------
// FP16 flash attention, BQ=128: each warp owns 16 full rows. P stays in
// registers (C-fragment == A-fragment after half2 pack). Softmax is pure
// quad-shuffle. One __syncthreads per KV tile. Bit-packed mask (L2-resident).
// ---------------------------------------------------------------------------
#define BQ 128
#define BKV 64
#define ATTN_NT (S_LEN / BKV)

#define SQ_OFF  0
#define SK_OFF  (128 * 272)                       // 34816
#define SVT_OFF (SK_OFF + 2 * 64 * 272)           // 69632
#define ATTN_SMEM_BYTES (SVT_OFF + 2 * 128 * 144) // 106496

__global__ __launch_bounds__(256, 1)
void attn_f16(const float* __restrict__ alibi,
              const uint32_t* __restrict__ maskw,
              __half* __restrict__ ctx)
{
    extern __shared__ unsigned char smem[];

    const int t    = threadIdx.x;
    const int warp = t >> 5, lane = t & 31;
    const int gid  = lane >> 2, tig = lane & 3;
    const int hh   = blockIdx.y;
    const int b    = hh / NHEADS;
    const int head = hh % NHEADS;
    const int q0   = blockIdx.x * BQ;
    const int mrow = warp * 16 + gid;             // local row (and +8)

    const uint32_t* mw = maskw + (size_t)b * (S_LEN * S_LEN / 32);

    // Q tile: 128 rows x 16 chunks (256B of halves per row)
    {
        const __half* qsrc = g_qkvh + (size_t)(b * S_LEN + q0) * 8192 + head * 256;
        for (int e = t; e < 2048; e += 256) {
            const int r = e >> 4, c = e & 15;
            cp16(smem + SQ_OFF + r * 272 + c * 16, qsrc + (size_t)r * 8192 + c * 8);
        }
    }

    const __half* ksrc0 = g_qkvh + (size_t)b * S_LEN * 8192 + head * 256 + 128;
    const __half* vsrc0 = g_vth + (size_t)hh * 128 * 2048;

    auto load_kv = [&](int st, int k0) {
        unsigned char* sK = smem + SK_OFF + st * (64 * 272);
        unsigned char* sV = smem + SVT_OFF + st * (128 * 144);
        for (int e = t; e < 2048; e += 256) {
            if (e < 1024) {   // K: 64 rows x 16 chunks
                const int r = e >> 4, c = e & 15;
                cp16(sK + r * 272 + c * 16,
                     ksrc0 + (size_t)(k0 + r) * 8192 + c * 8);
            } else {          // V^T: 128 d-rows x 8 chunks (128B per row)
                const int e2 = e - 1024;
                const int r = e2 >> 3, c = e2 & 7;
                cp16(sV + r * 144 + c * 16,
                     vsrc0 + (size_t)r * 2048 + k0 + c * 8);
            }
        }
    };

    load_kv(0, 0);
    CP_COMMIT();

    float o[16][4];
#pragma unroll
    for (int nt = 0; nt < 16; nt++)
#pragma unroll
        for (int c = 0; c < 4; c++) o[nt][c] = 0.f;

    // softmax state in registers; rows fully warp-owned
    float stMA = -FLT_MAX, stMB = -FLT_MAX;
    float stLA = 0.f, stLB = 0.f;

    for (int kt = 0; kt < ATTN_NT; kt++) {
        const int s  = kt & 1;
        const int k0 = kt * BKV;
        CP_WAIT(0);
        __syncthreads();                          // buffers rotated
        if (kt + 1 < ATTN_NT) load_kv(s ^ 1, k0 + BKV);
        CP_COMMIT();

        const uint32_t* Qp = (const uint32_t*)(smem + SQ_OFF);
        const uint32_t* Kp = (const uint32_t*)(smem + SK_OFF + s * (64 * 272));
        const uint32_t* Vp = (const uint32_t*)(smem + SVT_OFF + s * (128 * 144));

        // Phase 1: S = Q K^T, warp tile 16x64 (8 nt x 8 ks MMAs)
        float d[8][4];
#pragma unroll
        for (int nt = 0; nt < 8; nt++)
#pragma unroll
            for (int c = 0; c < 4; c++) d[nt][c] = 0.f;

#pragma unroll
        for (int ks = 0; ks < 8; ks++) {
            const uint32_t a0 = Qp[mrow * 68 + ks * 8 + tig];
            const uint32_t a1 = Qp[(mrow + 8) * 68 + ks * 8 + tig];
            const uint32_t a2 = Qp[mrow * 68 + ks * 8 + 4 + tig];
            const uint32_t a3 = Qp[(mrow + 8) * 68 + ks * 8 + 4 + tig];
#pragma unroll
            for (int nt = 0; nt < 8; nt++) {
                const int key = nt * 8 + gid;
                const uint32_t b0 = Kp[key * 68 + ks * 8 + tig];
                const uint32_t b1 = Kp[key * 68 + ks * 8 + 4 + tig];
                MMA_F16(d[nt], a0, a1, a2, a3, b0, b1);
            }
        }

        // alibi + bit-packed mask in registers (cols nt*8+2tig over 0..63)
        const int qrA = q0 + mrow, qrB = qrA + 8;
        const uint2 wA = *(const uint2*)&mw[qrA * 64 + (k0 >> 5)];
        const uint2 wB = *(const uint2*)&mw[qrB * 64 + (k0 >> 5)];
#pragma unroll
        for (int nt = 0; nt < 8; nt++) {
            const int colL = nt * 8 + tig * 2;
            const int kc   = k0 + colL;
            const float2 al = *(const float2*)(alibi + (size_t)hh * S_LEN + kc);
            const int sh = (nt & 3) * 8 + tig * 2;
            const uint32_t bA = ((nt < 4) ? wA.x : wA.y) >> sh;
            const uint32_t bB = ((nt < 4) ? wB.x : wB.y) >> sh;
            d[nt][0] = (bA & 1) ? -FLT_MAX : al.x + INV_NORM * d[nt][0];
            d[nt][1] = (bA & 2) ? -FLT_MAX : al.y + INV_NORM * d[nt][1];
            d[nt][2] = (bB & 1) ? -FLT_MAX : al.x + INV_NORM * d[nt][2];
            d[nt][3] = (bB & 2) ? -FLT_MAX : al.y + INV_NORM * d[nt][3];
        }

        // full row max via quad shuffle (row owned by this warp's quad)
        float mAp = -FLT_MAX, mBp = -FLT_MAX;
#pragma unroll
        for (int nt = 0; nt < 8; nt++) {
            mAp = fmaxf(mAp, fmaxf(d[nt][0], d[nt][1]));
            mBp = fmaxf(mBp, fmaxf(d[nt][2], d[nt][3]));
        }
        mAp = fmaxf(mAp, __shfl_xor_sync(0xffffffffu, mAp, 1));
        mAp = fmaxf(mAp, __shfl_xor_sync(0xffffffffu, mAp, 2));
        mBp = fmaxf(mBp, __shfl_xor_sync(0xffffffffu, mBp, 1));
        mBp = fmaxf(mBp, __shfl_xor_sync(0xffffffffu, mBp, 2));

        const float mnA = fmaxf(stMA, mAp);
        const float mnB = fmaxf(stMB, mBp);
        const float cA = __expf(stMA - mnA);
        const float cB = __expf(stMB - mnB);
        stMA = mnA; stMB = mnB;

        // exp + pack P into A-fragments (registers only)
        uint32_t paA[8], paB[8];
        float sumA = 0.f, sumB = 0.f;
#pragma unroll
        for (int nt = 0; nt < 8; nt++) {
            float p00 = __expf(d[nt][0] - mnA);
            float p01 = __expf(d[nt][1] - mnA);
            float p10 = __expf(d[nt][2] - mnB);
            float p11 = __expf(d[nt][3] - mnB);
            sumA += p00 + p01;
            sumB += p10 + p11;
            __half2 hA = __float22half2_rn(make_float2(p00, p01));
            __half2 hB = __float22half2_rn(make_float2(p10, p11));
            paA[nt] = *(uint32_t*)&hA;
            paB[nt] = *(uint32_t*)&hB;
        }
        sumA += __shfl_xor_sync(0xffffffffu, sumA, 1);
        sumA += __shfl_xor_sync(0xffffffffu, sumA, 2);
        sumB += __shfl_xor_sync(0xffffffffu, sumB, 1);
        sumB += __shfl_xor_sync(0xffffffffu, sumB, 2);
        stLA = stLA * cA + sumA;
        stLB = stLB * cB + sumB;

        // Phase 3: O = O*c + P @ V (warp tile 16x128, A from registers)
#pragma unroll
        for (int nt = 0; nt < 16; nt++) {
            o[nt][0] *= cA; o[nt][1] *= cA;
            o[nt][2] *= cB; o[nt][3] *= cB;
        }
#pragma unroll
        for (int ks = 0; ks < 4; ks++) {
            const uint32_t a0 = paA[2 * ks];
            const uint32_t a1 = paB[2 * ks];
            const uint32_t a2 = paA[2 * ks + 1];
            const uint32_t a3 = paB[2 * ks + 1];
#pragma unroll
            for (int nt = 0; nt < 16; nt++) {
                const int colD = nt * 8 + gid;
                const uint32_t b0 = Vp[colD * 36 + ks * 8 + tig];
                const uint32_t b1 = Vp[colD * 36 + ks * 8 + 4 + tig];
                MMA_F16(o[nt], a0, a1, a2, a3, b0, b1);
            }
        }
    }

    // epilogue: warp-local l, divide, store
    {
        const float lA = 1.0f / stLA;
        const float lB = 1.0f / stLB;
        const int rowA = b * S_LEN + q0 + mrow;
#pragma unroll
        for (int nt = 0; nt < 16; nt++) {
            const int col = head * HEADD + nt * 8 + tig * 2;
            *(__half2*)&ctx[(size_t)rowA * HDIM + col] =
                __float22half2_rn(make_float2(o[nt][0] * lA, o[nt][1] * lA));
            *(__half2*)&ctx[(size_t)(rowA + 8) * HDIM + col] =
                __float22half2_rn(make_float2(o[nt][2] * lB, o[nt][3] * lB));
        }
    }
}

// ---------------------------------------------------------------------------
extern "C" void kernel_launch(void* const* d_in, const int* in_sizes, int n_in,
                              void* d_out, int out_size)
{
    const float* hs    = (const float*)d_in[0];
    const float* resid = (const float*)d_in[1];
    const float* alibi = (const float*)d_in[2];
    const void*  maskp = d_in[3];
    const float* qkv_w = (const float*)d_in[4];
    const float* qkv_b = (const float*)d_in[5];
    const float* dw    = (const float*)d_in[6];
    const float* db    = (const float*)d_in[7];
    float* out = (float*)d_out;

    __half *rw, *rhs, *rw2, *ctxh;
    uint32_t* maskw;
    int *fi, *ff;
    cudaGetSymbolAddress((void**)&rw,    g_rwh);
    cudaGetSymbolAddress((void**)&rhs,   g_rhsh);
    cudaGetSymbolAddress((void**)&rw2,   g_rw2h);
    cudaGetSymbolAddress((void**)&ctxh,  g_ctxh);
    cudaGetSymbolAddress((void**)&maskw, g_maskw);
    cudaGetSymbolAddress((void**)&fi,    g_all_int01);
    cudaGetSymbolAddress((void**)&ff,    g_all_f01);

    cudaFuncSetAttribute(gemm_f16, cudaFuncAttributeMaxDynamicSharedMemorySize,
                         GEMM_SMEM_BYTES);
    cudaFuncSetAttribute(attn_f16, cudaFuncAttributeMaxDynamicSharedMemorySize,
                         ATTN_SMEM_BYTES);

    // flag init via async memset (graph-capturable, nonzero == true)
    cudaMemsetAsync(fi, 1, sizeof(int));
    cudaMemsetAsync(ff, 1, sizeof(int));
    k_detect<<<256, 256>>>((const int*)maskp, in_sizes[3] / 4);
    k_pack_bits<<<512, 256>>>(maskp, maskw, MASK_WORDS);

    // fused f32 -> half converts (qkv_w, hs, dense_w), block-range segmented
    {
        const int n1 = (int)((size_t)QKV_N * HDIM / 4);   // 12582912
        const int n2 = (int)((size_t)M_ROWS * HDIM / 4);  // 4194304
        const int n3 = (int)((size_t)HDIM * HDIM / 4);    // 4194304
        const int total_blks = 8192;
        // proportional block split (n1:n2:n3 = 3:1:1)
        const int blks1 = 4916, blks2 = 1638;             // rest = 1638
        k_cvt3<<<total_blks, 256>>>(
            (const float4*)qkv_w, (uint2*)rw,  n1,
            (const float4*)hs,    (uint2*)rhs, n2,
            (const float4*)dw,    (uint2*)rw2, n3,
            blks1, blks2);
    }

    // QKV projection (fp16 tensor cores) -> g_qkvh (q,k) + g_vth (V^T)
    gemm_f16<<<dim3(QKV_N / 128, M_ROWS / 128), 256, GEMM_SMEM_BYTES>>>(
        rhs, rw, qkv_b, nullptr, nullptr, M_ROWS, QKV_N, HDIM, 1);

    // Flash attention (BQ=128, register-resident P, bit mask) -> g_ctxh
    attn_f16<<<dim3(S_LEN / BQ, BATCH * NHEADS), 256, ATTN_SMEM_BYTES>>>(
        alibi, maskw, ctxh);

    // Output projection + bias + residual (fp16 tensor cores, f32 out)
    gemm_f16<<<dim3(HDIM / 128, M_ROWS / 128), 256, GEMM_SMEM_BYTES>>>(
        ctxh, rw2, db, resid, out, M_ROWS, HDIM, HDIM, 0);
}

// round 16
// speedup vs baseline: 1.0902x; 1.0006x over previous
#include <cuda_runtime.h>
#include <cuda_fp16.h>
#include <cfloat>
#include <cstdint>

// Problem constants
#define S_LEN   2048
#define BATCH   2
#define HDIM    4096
#define NHEADS  32
#define HEADD   128
#define M_ROWS  4096            // B*S
#define QKV_N   12288           // 3*H
#define INV_NORM 0.08838834764831845f   // 1/sqrt(128)
#define MASK_WORDS (BATCH * S_LEN * S_LEN / 32)   // 262144 u32 = 1MB

// Scratch (allocation-free rule: __device__ globals). All half-precision.
__device__ __half g_qkvh[(size_t)M_ROWS * 8192];        // [row][head][{q,k}][128]
__device__ __half g_vth [(size_t)64 * 128 * 2048];      // [b*NH+h][d][s] (V^T)
__device__ __half g_rwh [(size_t)QKV_N * HDIM];         // qkv_w half
__device__ __half g_rhsh[(size_t)M_ROWS * HDIM];        // hs half
__device__ __half g_rw2h[(size_t)HDIM * HDIM];          // dense_w half
__device__ __half g_ctxh[(size_t)M_ROWS * HDIM];        // ctx half
__device__ uint32_t g_maskw[MASK_WORDS];                // bit-packed mask
__device__ int   g_all_int01;
__device__ int   g_all_f01;

// ---------------------------------------------------------------------------
__global__ void k_detect(const int* __restrict__ w, int n) {
    for (int i = blockIdx.x * blockDim.x + threadIdx.x; i < n;
         i += gridDim.x * blockDim.x) {
        int v = w[i];
        if ((unsigned)v > 1u) g_all_int01 = 0;
        float f = __int_as_float(v);
        if (!(f == 0.0f || f == 1.0f)) g_all_f01 = 0;
    }
}

// Pack mask (any wire dtype) -> 1 bit per element
__global__ void k_pack_bits(const void* __restrict__ in,
                            uint32_t* __restrict__ out, int nwords) {
    const int mtype = g_all_int01 ? 1 : (g_all_f01 ? 2 : 0);
    for (int w = blockIdx.x * blockDim.x + threadIdx.x; w < nwords;
         w += gridDim.x * blockDim.x) {
        uint32_t bits = 0;
        if (mtype == 1) {
            const int4* p = (const int4*)in + (size_t)w * 8;
#pragma unroll
            for (int j = 0; j < 8; j++) {
                int4 v = p[j];
                bits |= (v.x != 0 ? 1u : 0u) << (j * 4 + 0);
                bits |= (v.y != 0 ? 1u : 0u) << (j * 4 + 1);
                bits |= (v.z != 0 ? 1u : 0u) << (j * 4 + 2);
                bits |= (v.w != 0 ? 1u : 0u) << (j * 4 + 3);
            }
        } else if (mtype == 2) {
            const float4* p = (const float4*)in + (size_t)w * 8;
#pragma unroll
            for (int j = 0; j < 8; j++) {
                float4 v = p[j];
                bits |= (v.x != 0.f ? 1u : 0u) << (j * 4 + 0);
                bits |= (v.y != 0.f ? 1u : 0u) << (j * 4 + 1);
                bits |= (v.z != 0.f ? 1u : 0u) << (j * 4 + 2);
                bits |= (v.w != 0.f ? 1u : 0u) << (j * 4 + 3);
            }
        } else {
            const uint4* p = (const uint4*)in + (size_t)w * 2;
#pragma unroll
            for (int j = 0; j < 2; j++) {
                uint4 v = p[j];
                const uint32_t ws[4] = {v.x, v.y, v.z, v.w};
#pragma unroll
                for (int q = 0; q < 4; q++)
#pragma unroll
                    for (int bb = 0; bb < 4; bb++)
                        bits |= (((ws[q] >> (bb * 8)) & 0xFFu) != 0 ? 1u : 0u)
                                << (j * 16 + q * 4 + bb);
            }
        }
        out[w] = bits;
    }
}

// Fused f32 -> packed half2 conversion; block-range segmented (no per-iter branch)
__global__ void k_cvt3(const float4* __restrict__ i1, uint2* __restrict__ o1, int n1,
                       const float4* __restrict__ i2, uint2* __restrict__ o2, int n2,
                       const float4* __restrict__ i3, uint2* __restrict__ o3, int n3,
                       int blks1, int blks2)
{
    const float4* src; uint2* dst; int n; int blk0; int nblks;
    if ((int)blockIdx.x < blks1) {
        src = i1; dst = o1; n = n1; blk0 = 0; nblks = blks1;
    } else if ((int)blockIdx.x < blks1 + blks2) {
        src = i2; dst = o2; n = n2; blk0 = blks1; nblks = blks2;
    } else {
        src = i3; dst = o3; n = n3; blk0 = blks1 + blks2;
        nblks = gridDim.x - blks1 - blks2;
    }
    const int stride = nblks * blockDim.x;
    for (int i = ((int)blockIdx.x - blk0) * blockDim.x + threadIdx.x; i < n;
         i += stride) {
        float4 v = src[i];
        __half2 lo = __float22half2_rn(make_float2(v.x, v.y));
        __half2 hi = __float22half2_rn(make_float2(v.z, v.w));
        uint2 o;
        o.x = *(uint32_t*)&lo;
        o.y = *(uint32_t*)&hi;
        dst[i] = o;
    }
}

// ---------------------------------------------------------------------------
// cp.async helpers
// ---------------------------------------------------------------------------
__device__ __forceinline__ void cp16(void* dst, const void* src) {
    uint32_t d = (uint32_t)__cvta_generic_to_shared(dst);
    asm volatile("cp.async.cg.shared.global [%0], [%1], 16;" :: "r"(d), "l"(src));
}
#define CP_COMMIT()  asm volatile("cp.async.commit_group;")
#define CP_WAIT(n)   asm volatile("cp.async.wait_group %0;" :: "n"(n))

// fp16 MMA m16n8k16, f32 accumulate
#define MMA_F16(D, a0, a1, a2, a3, b0, b1)                                    \
    asm volatile(                                                             \
        "mma.sync.aligned.m16n8k16.row.col.f32.f16.f16.f32 "                  \
        "{%0,%1,%2,%3}, {%4,%5,%6,%7}, {%8,%9}, {%0,%1,%2,%3};"               \
        : "+f"(D[0]), "+f"(D[1]), "+f"(D[2]), "+f"(D[3])                      \
        : "r"(a0), "r"(a1), "r"(a2), "r"(a3), "r"(b0), "r"(b1))

// ---------------------------------------------------------------------------
// FP16 GEMM (NT), 3-stage cp.async pipeline.  (R9/R13 proven version)
// Block 128x128, K-tile 64 halves, 256 threads (8 warps 4x2), warp tile 32x64.
// mode 0: f32 out C = acc + bias + resid
// mode 1: qkv split -> g_qkvh (q,k packed half) + g_vth (V^T scatter stores)
// ---------------------------------------------------------------------------
#define GBK 64                       // K-tile in halves
#define GPAD 36                      // row stride in uint32 (144B)
#define GROWB 144                    // row stride bytes
#define GSTG_B (256 * GROWB)         // 36864 B per stage (A 128 rows + B 128)
#define GNSTG 3
#define GEMM_SMEM_BYTES (GNSTG * GSTG_B)

__global__ __launch_bounds__(256, 2)
void gemm_f16(const __half* __restrict__ A, const __half* __restrict__ W,
              const float* __restrict__ bias, const float* __restrict__ resid,
              float* __restrict__ C, int M, int N, int K, int mode)
{
    extern __shared__ unsigned char gsmb[];

    const int t    = threadIdx.x;
    const int warp = t >> 5;
    const int lane = t & 31;
    const int gid  = lane >> 2;
    const int tig  = lane & 3;
    const int wm   = (warp >> 1) * 32;
    const int wn   = (warp & 1) * 64;

    const int bm = blockIdx.y * 128;
    const int bn = blockIdx.x * 128;
    const int NT = K / GBK;

    float d[2][8][4];
#pragma unroll
    for (int i = 0; i < 2; i++)
#pragma unroll
        for (int j = 0; j < 8; j++)
#pragma unroll
            for (int c = 0; c < 4; c++) d[i][j][c] = 0.f;

    // loader: 256 rows x 8 chunks (16B) = 2048 tasks, 8 per thread
    auto load_stage = [&](int st, int kk0) {
        unsigned char* stg = gsmb + st * GSTG_B;
#pragma unroll
        for (int i = 0; i < 8; i++) {
            const int e = i * 256 + t;
            const int r = e >> 3, c = e & 7;
            const __half* src = (r < 128)
                ? A + (size_t)(bm + r) * K + kk0 + c * 8
                : W + (size_t)(bn + r - 128) * K + kk0 + c * 8;
            cp16(stg + r * GROWB + c * 16, src);
        }
    };

    load_stage(0, 0);    CP_COMMIT();
    load_stage(1, GBK);  CP_COMMIT();

    for (int kt = 0; kt < NT; kt++) {
        const int s = kt % GNSTG;
        CP_WAIT(1);
        __syncthreads();
        if (kt + 2 < NT) load_stage((kt + 2) % GNSTG, (kt + 2) * GBK);
        CP_COMMIT();

        const uint32_t* As = (const uint32_t*)(gsmb + s * GSTG_B);
        const uint32_t* Ws = As + 128 * GPAD;

#pragma unroll
        for (int ks = 0; ks < 4; ks++) {
            uint32_t a[2][4];
#pragma unroll
            for (int mt = 0; mt < 2; mt++) {
                const int r = wm + mt * 16 + gid;
                a[mt][0] = As[r * GPAD + ks * 8 + tig];
                a[mt][1] = As[(r + 8) * GPAD + ks * 8 + tig];
                a[mt][2] = As[r * GPAD + ks * 8 + 4 + tig];
                a[mt][3] = As[(r + 8) * GPAD + ks * 8 + 4 + tig];
            }
            uint32_t b[8][2];
#pragma unroll
            for (int nt = 0; nt < 8; nt++) {
                const int r = wn + nt * 8 + gid;
                b[nt][0] = Ws[r * GPAD + ks * 8 + tig];
                b[nt][1] = Ws[r * GPAD + ks * 8 + 4 + tig];
            }
#pragma unroll
            for (int mt = 0; mt < 2; mt++)
#pragma unroll
                for (int nt = 0; nt < 8; nt++)
                    MMA_F16(d[mt][nt], a[mt][0], a[mt][1], a[mt][2], a[mt][3],
                            b[nt][0], b[nt][1]);
        }
    }

    // Epilogue (scatter version — proven)
#pragma unroll
    for (int mt = 0; mt < 2; mt++) {
        const int r0 = bm + wm + mt * 16 + gid;
#pragma unroll
        for (int nt = 0; nt < 8; nt++) {
            const int col = bn + wn + nt * 8 + tig * 2;
            const float b0 = bias[col], b1 = bias[col + 1];
            float v00 = d[mt][nt][0] + b0, v01 = d[mt][nt][1] + b1;
            float v10 = d[mt][nt][2] + b0, v11 = d[mt][nt][3] + b1;
            if (mode == 0) {
                size_t i0 = (size_t)r0 * N + col;
                size_t i1 = (size_t)(r0 + 8) * N + col;
                const float2 rr0 = *(const float2*)(resid + i0);
                const float2 rr1 = *(const float2*)(resid + i1);
                *(float2*)(C + i0) = make_float2(v00 + rr0.x, v01 + rr0.y);
                *(float2*)(C + i1) = make_float2(v10 + rr1.x, v11 + rr1.y);
            } else {
                const int head = col / 384;
                const int rem  = col - head * 384;
                const int part = rem >> 7;
                const int dd   = rem & 127;
                if (part < 2) {
                    size_t base = (size_t)r0 * 8192 + head * 256 + part * 128 + dd;
                    *(__half2*)&g_qkvh[base] =
                        __float22half2_rn(make_float2(v00, v01));
                    *(__half2*)&g_qkvh[base + (size_t)8 * 8192] =
                        __float22half2_rn(make_float2(v10, v11));
                } else {
                    const int bb = r0 >> 11, s0 = r0 & 2047;
                    size_t vb = ((size_t)(bb * 32 + head) * 128 + dd) * 2048;
                    g_vth[vb + s0]            = __float2half_rn(v00);
                    g_vth[vb + 2048 + s0]     = __float2half_rn(v01);
                    g_vth[vb + s0 + 8]        = __float2half_rn(v10);
                    g_vth[vb + 2048 + s0 + 8] = __float2half_rn(v11);
                }
            }
        }
    }
}

// ---------------------------------------------------------------------------
// FP16 flash attention, BQ=128: each warp owns 16 full rows. P stays in
// registers (C-fragment == A-fragment after half2 pack). Softmax is pure
// quad-shuffle. One __syncthreads per KV tile. Bit-packed mask (L2-resident).
// ---------------------------------------------------------------------------
#define BQ 128
#define BKV 64
#define ATTN_NT (S_LEN / BKV)

#define SQ_OFF  0
#define SK_OFF  (128 * 272)                       // 34816
#define SVT_OFF (SK_OFF + 2 * 64 * 272)           // 69632
#define ATTN_SMEM_BYTES (SVT_OFF + 2 * 128 * 144) // 106496

__global__ __launch_bounds__(256, 1)
void attn_f16(const float* __restrict__ alibi,
              const uint32_t* __restrict__ maskw,
              __half* __restrict__ ctx)
{
    extern __shared__ unsigned char smem[];

    const int t    = threadIdx.x;
    const int warp = t >> 5, lane = t & 31;
    const int gid  = lane >> 2, tig = lane & 3;
    const int hh   = blockIdx.y;
    const int b    = hh / NHEADS;
    const int head = hh % NHEADS;
    const int q0   = blockIdx.x * BQ;
    const int mrow = warp * 16 + gid;             // local row (and +8)

    const uint32_t* mw = maskw + (size_t)b * (S_LEN * S_LEN / 32);

    // Q tile: 128 rows x 16 chunks (256B of halves per row)
    {
        const __half* qsrc = g_qkvh + (size_t)(b * S_LEN + q0) * 8192 + head * 256;
        for (int e = t; e < 2048; e += 256) {
            const int r = e >> 4, c = e & 15;
            cp16(smem + SQ_OFF + r * 272 + c * 16, qsrc + (size_t)r * 8192 + c * 8);
        }
    }

    const __half* ksrc0 = g_qkvh + (size_t)b * S_LEN * 8192 + head * 256 + 128;
    const __half* vsrc0 = g_vth + (size_t)hh * 128 * 2048;

    auto load_kv = [&](int st, int k0) {
        unsigned char* sK = smem + SK_OFF + st * (64 * 272);
        unsigned char* sV = smem + SVT_OFF + st * (128 * 144);
        for (int e = t; e < 2048; e += 256) {
            if (e < 1024) {   // K: 64 rows x 16 chunks
                const int r = e >> 4, c = e & 15;
                cp16(sK + r * 272 + c * 16,
                     ksrc0 + (size_t)(k0 + r) * 8192 + c * 8);
            } else {          // V^T: 128 d-rows x 8 chunks (128B per row)
                const int e2 = e - 1024;
                const int r = e2 >> 3, c = e2 & 7;
                cp16(sV + r * 144 + c * 16,
                     vsrc0 + (size_t)r * 2048 + k0 + c * 8);
            }
        }
    };

    load_kv(0, 0);
    CP_COMMIT();

    float o[16][4];
#pragma unroll
    for (int nt = 0; nt < 16; nt++)
#pragma unroll
        for (int c = 0; c < 4; c++) o[nt][c] = 0.f;

    // softmax state in registers; rows fully warp-owned
    float stMA = -FLT_MAX, stMB = -FLT_MAX;
    float stLA = 0.f, stLB = 0.f;

    for (int kt = 0; kt < ATTN_NT; kt++) {
        const int s  = kt & 1;
        const int k0 = kt * BKV;
        CP_WAIT(0);
        __syncthreads();                          // buffers rotated
        if (kt + 1 < ATTN_NT) load_kv(s ^ 1, k0 + BKV);
        CP_COMMIT();

        const uint32_t* Qp = (const uint32_t*)(smem + SQ_OFF);
        const uint32_t* Kp = (const uint32_t*)(smem + SK_OFF + s * (64 * 272));
        const uint32_t* Vp = (const uint32_t*)(smem + SVT_OFF + s * (128 * 144));

        // Phase 1: S = Q K^T, warp tile 16x64 (8 nt x 8 ks MMAs)
        float d[8][4];
#pragma unroll
        for (int nt = 0; nt < 8; nt++)
#pragma unroll
            for (int c = 0; c < 4; c++) d[nt][c] = 0.f;

#pragma unroll
        for (int ks = 0; ks < 8; ks++) {
            const uint32_t a0 = Qp[mrow * 68 + ks * 8 + tig];
            const uint32_t a1 = Qp[(mrow + 8) * 68 + ks * 8 + tig];
            const uint32_t a2 = Qp[mrow * 68 + ks * 8 + 4 + tig];
            const uint32_t a3 = Qp[(mrow + 8) * 68 + ks * 8 + 4 + tig];
#pragma unroll
            for (int nt = 0; nt < 8; nt++) {
                const int key = nt * 8 + gid;
                const uint32_t b0 = Kp[key * 68 + ks * 8 + tig];
                const uint32_t b1 = Kp[key * 68 + ks * 8 + 4 + tig];
                MMA_F16(d[nt], a0, a1, a2, a3, b0, b1);
            }
        }

        // alibi + bit-packed mask in registers (cols nt*8+2tig over 0..63)
        const int qrA = q0 + mrow, qrB = qrA + 8;
        const uint2 wA = *(const uint2*)&mw[qrA * 64 + (k0 >> 5)];
        const uint2 wB = *(const uint2*)&mw[qrB * 64 + (k0 >> 5)];
#pragma unroll
        for (int nt = 0; nt < 8; nt++) {
            const int colL = nt * 8 + tig * 2;
            const int kc   = k0 + colL;
            const float2 al = *(const float2*)(alibi + (size_t)hh * S_LEN + kc);
            const int sh = (nt & 3) * 8 + tig * 2;
            const uint32_t bA = ((nt < 4) ? wA.x : wA.y) >> sh;
            const uint32_t bB = ((nt < 4) ? wB.x : wB.y) >> sh;
            d[nt][0] = (bA & 1) ? -FLT_MAX : al.x + INV_NORM * d[nt][0];
            d[nt][1] = (bA & 2) ? -FLT_MAX : al.y + INV_NORM * d[nt][1];
            d[nt][2] = (bB & 1) ? -FLT_MAX : al.x + INV_NORM * d[nt][2];
            d[nt][3] = (bB & 2) ? -FLT_MAX : al.y + INV_NORM * d[nt][3];
        }

        // full row max via quad shuffle (row owned by this warp's quad)
        float mAp = -FLT_MAX, mBp = -FLT_MAX;
#pragma unroll
        for (int nt = 0; nt < 8; nt++) {
            mAp = fmaxf(mAp, fmaxf(d[nt][0], d[nt][1]));
            mBp = fmaxf(mBp, fmaxf(d[nt][2], d[nt][3]));
        }
        mAp = fmaxf(mAp, __shfl_xor_sync(0xffffffffu, mAp, 1));
        mAp = fmaxf(mAp, __shfl_xor_sync(0xffffffffu, mAp, 2));
        mBp = fmaxf(mBp, __shfl_xor_sync(0xffffffffu, mBp, 1));
        mBp = fmaxf(mBp, __shfl_xor_sync(0xffffffffu, mBp, 2));

        const float mnA = fmaxf(stMA, mAp);
        const float mnB = fmaxf(stMB, mBp);
        const float cA = __expf(stMA - mnA);
        const float cB = __expf(stMB - mnB);
        stMA = mnA; stMB = mnB;

        // exp + pack P into A-fragments (registers only)
        uint32_t paA[8], paB[8];
        float sumA = 0.f, sumB = 0.f;
#pragma unroll
        for (int nt = 0; nt < 8; nt++) {
            float p00 = __expf(d[nt][0] - mnA);
            float p01 = __expf(d[nt][1] - mnA);
            float p10 = __expf(d[nt][2] - mnB);
            float p11 = __expf(d[nt][3] - mnB);
            sumA += p00 + p01;
            sumB += p10 + p11;
            __half2 hA = __float22half2_rn(make_float2(p00, p01));
            __half2 hB = __float22half2_rn(make_float2(p10, p11));
            paA[nt] = *(uint32_t*)&hA;
            paB[nt] = *(uint32_t*)&hB;
        }
        sumA += __shfl_xor_sync(0xffffffffu, sumA, 1);
        sumA += __shfl_xor_sync(0xffffffffu, sumA, 2);
        sumB += __shfl_xor_sync(0xffffffffu, sumB, 1);
        sumB += __shfl_xor_sync(0xffffffffu, sumB, 2);
        stLA = stLA * cA + sumA;
        stLB = stLB * cB + sumB;

        // Phase 3: O = O*c + P @ V (warp tile 16x128, A from registers)
#pragma unroll
        for (int nt = 0; nt < 16; nt++) {
            o[nt][0] *= cA; o[nt][1] *= cA;
            o[nt][2] *= cB; o[nt][3] *= cB;
        }
#pragma unroll
        for (int ks = 0; ks < 4; ks++) {
            const uint32_t a0 = paA[2 * ks];
            const uint32_t a1 = paB[2 * ks];
            const uint32_t a2 = paA[2 * ks + 1];
            const uint32_t a3 = paB[2 * ks + 1];
#pragma unroll
            for (int nt = 0; nt < 16; nt++) {
                const int colD = nt * 8 + gid;
                const uint32_t b0 = Vp[colD * 36 + ks * 8 + tig];
                const uint32_t b1 = Vp[colD * 36 + ks * 8 + 4 + tig];
                MMA_F16(o[nt], a0, a1, a2, a3, b0, b1);
            }
        }
    }

    // epilogue: warp-local l, divide, store
    {
        const float lA = 1.0f / stLA;
        const float lB = 1.0f / stLB;
        const int rowA = b * S_LEN + q0 + mrow;
#pragma unroll
        for (int nt = 0; nt < 16; nt++) {
            const int col = head * HEADD + nt * 8 + tig * 2;
            *(__half2*)&ctx[(size_t)rowA * HDIM + col] =
                __float22half2_rn(make_float2(o[nt][0] * lA, o[nt][1] * lA));
            *(__half2*)&ctx[(size_t)(rowA + 8) * HDIM + col] =
                __float22half2_rn(make_float2(o[nt][2] * lB, o[nt][3] * lB));
        }
    }
}

// ---------------------------------------------------------------------------
extern "C" void kernel_launch(void* const* d_in, const int* in_sizes, int n_in,
                              void* d_out, int out_size)
{
    const float* hs    = (const float*)d_in[0];
    const float* resid = (const float*)d_in[1];
    const float* alibi = (const float*)d_in[2];
    const void*  maskp = d_in[3];
    const float* qkv_w = (const float*)d_in[4];
    const float* qkv_b = (const float*)d_in[5];
    const float* dw    = (const float*)d_in[6];
    const float* db    = (const float*)d_in[7];
    float* out = (float*)d_out;

    __half *rw, *rhs, *rw2, *ctxh;
    uint32_t* maskw;
    int *fi, *ff;
    cudaGetSymbolAddress((void**)&rw,    g_rwh);
    cudaGetSymbolAddress((void**)&rhs,   g_rhsh);
    cudaGetSymbolAddress((void**)&rw2,   g_rw2h);
    cudaGetSymbolAddress((void**)&ctxh,  g_ctxh);
    cudaGetSymbolAddress((void**)&maskw, g_maskw);
    cudaGetSymbolAddress((void**)&fi,    g_all_int01);
    cudaGetSymbolAddress((void**)&ff,    g_all_f01);

    cudaFuncSetAttribute(gemm_f16, cudaFuncAttributeMaxDynamicSharedMemorySize,
                         GEMM_SMEM_BYTES);
    cudaFuncSetAttribute(attn_f16, cudaFuncAttributeMaxDynamicSharedMemorySize,
                         ATTN_SMEM_BYTES);

    // flag init via async memset (graph-capturable, nonzero == true)
    cudaMemsetAsync(fi, 1, sizeof(int));
    cudaMemsetAsync(ff, 1, sizeof(int));
    k_detect<<<256, 256>>>((const int*)maskp, in_sizes[3] / 4);
    k_pack_bits<<<512, 256>>>(maskp, maskw, MASK_WORDS);

    // fused f32 -> half converts (qkv_w, hs, dense_w), block-range segmented
    {
        const int n1 = (int)((size_t)QKV_N * HDIM / 4);   // 12582912
        const int n2 = (int)((size_t)M_ROWS * HDIM / 4);  // 4194304
        const int n3 = (int)((size_t)HDIM * HDIM / 4);    // 4194304
        const int total_blks = 8192;
        // proportional block split (n1:n2:n3 = 3:1:1)
        const int blks1 = 4916, blks2 = 1638;             // rest = 1638
        k_cvt3<<<total_blks, 256>>>(
            (const float4*)qkv_w, (uint2*)rw,  n1,
            (const float4*)hs,    (uint2*)rhs, n2,
            (const float4*)dw,    (uint2*)rw2, n3,
            blks1, blks2);
    }

    // QKV projection (fp16 tensor cores) -> g_qkvh (q,k) + g_vth (V^T)
    gemm_f16<<<dim3(QKV_N / 128, M_ROWS / 128), 256, GEMM_SMEM_BYTES>>>(
        rhs, rw, qkv_b, nullptr, nullptr, M_ROWS, QKV_N, HDIM, 1);

    // Flash attention (BQ=128, register-resident P, bit mask) -> g_ctxh
    attn_f16<<<dim3(S_LEN / BQ, BATCH * NHEADS), 256, ATTN_SMEM_BYTES>>>(
        alibi, maskw, ctxh);

    // Output projection + bias + residual (fp16 tensor cores, f32 out)
    gemm_f16<<<dim3(HDIM / 128, M_ROWS / 128), 256, GEMM_SMEM_BYTES>>>(
        ctxh, rw2, db, resid, out, M_ROWS, HDIM, HDIM, 0);
}